// round 11
// baseline (speedup 1.0000x reference)
#include <cuda_runtime.h>

#define T_ 3
#define H_ 4
#define DIN 64
#define FEAT_IN 192     /* T_*DIN */
#define FDIM 384        /* H_ * T_*32 */
#define EF_ 64
#define NET 5
#define MAXN 50000
#define MAXE 400000
#define NEG_SLOPE 0.2f
#define PADN 36

#define GBLK 148
#define GTHR 512

typedef unsigned long long ull;

__device__ float g_ft[(size_t)MAXN * FDIM];
__device__ float g_el[MAXN * H_];
__device__ float g_er[MAXN * H_];
__device__ float g_ee[32];
__device__ int   g_cnt[MAXN + 1];
__device__ int   g_off[MAXN + 1];
__device__ int   g_cur[MAXN + 1];
__device__ int   g_eidx[MAXE];
__device__ int   g_part[256];
__device__ unsigned g_barc[8];   // zero-init; generation barrier counters

__device__ __forceinline__ ull pack2(float x, float y) {
    ull r; asm("mov.b64 %0, {%1,%2};" : "=l"(r) : "f"(x), "f"(y)); return r;
}
__device__ __forceinline__ ull fma2(ull a, ull b, ull c) {
    ull d; asm("fma.rn.f32x2 %0, %1, %2, %3;" : "=l"(d) : "l"(a), "l"(b), "l"(c)); return d;
}
__device__ __forceinline__ float lo2(ull v) { return __uint_as_float((unsigned)(v & 0xffffffffull)); }
__device__ __forceinline__ float hi2(ull v) { return __uint_as_float((unsigned)(v >> 32)); }
__device__ __forceinline__ void stcs32(float* p, float v) {
    asm volatile("st.global.cs.f32 [%0], %1;" :: "l"(p), "f"(v) : "memory");
}
__device__ __forceinline__ float lrelu(float x) { return x >= 0.f ? x : NEG_SLOPE * x; }
__device__ __forceinline__ float pick4(float4 v, int h) {
    float r = v.x;
    r = (h == 1) ? v.y : r;
    r = (h == 2) ? v.z : r;
    r = (h == 3) ? v.w : r;
    return r;
}

// generation-based global barrier: counter only ever increments (safe across
// graph replays); all 148 blocks are co-resident (grid == #SMs).
__device__ __forceinline__ void gbar(int i) {
    __syncthreads();
    if (threadIdx.x == 0) {
        __threadfence();
        unsigned gen = atomicAdd(&g_barc[i], 1u) / GBLK;
        unsigned tgt = (gen + 1u) * GBLK;
        unsigned v;
        do {
            asm volatile("ld.acquire.gpu.u32 %0, [%1];" : "=r"(v) : "l"(&g_barc[i]));
        } while (v < tgt);
    }
    __syncthreads();
}

// ---------------------------------------------------------------------------
// k_csr: fused zero + count + scan + scatter (persistent, 148 blocks)
// ---------------------------------------------------------------------------
__global__ void __launch_bounds__(GTHR) k_csr(const int* __restrict__ dst, int E, int N) {
    __shared__ int wsum[16];
    __shared__ int sm2[256];
    int tid = threadIdx.x, b = blockIdx.x;
    int gt = b * GTHR + tid;
    const int GT = GBLK * GTHR;

    // phase 0: zero counts
    for (int i = gt; i <= N; i += GT) g_cnt[i] = 0;
    gbar(0);

    // phase 1: count
    int quads = E >> 2;
    for (int i = gt; i < quads; i += GT) {
        int4 d = ((const int4*)dst)[i];
        atomicAdd(&g_cnt[d.x], 1);
        atomicAdd(&g_cnt[d.y], 1);
        atomicAdd(&g_cnt[d.z], 1);
        atomicAdd(&g_cnt[d.w], 1);
    }
    if (gt < (E & 3)) atomicAdd(&g_cnt[(E & ~3) + gt], 1);
    gbar(1);

    // phase 2a: block-local exclusive scan over segment [b*SEG, ...)
    int SEG = (N + 1 + GBLK - 1) / GBLK;          // 338 for N=50000 (<= GTHR)
    int idx = b * SEG + tid;
    int lane = tid & 31, w = tid >> 5;
    int x = (tid < SEG && idx <= N) ? g_cnt[idx] : 0;
    int incl = x;
#pragma unroll
    for (int d = 1; d < 32; d <<= 1) {
        int y = __shfl_up_sync(0xffffffffu, incl, d);
        if (lane >= d) incl += y;
    }
    if (lane == 31) wsum[w] = incl;
    __syncthreads();
    if (tid < 32) {
        int s = (tid < 16) ? wsum[tid] : 0;
#pragma unroll
        for (int d = 1; d < 16; d <<= 1) {
            int y = __shfl_up_sync(0xffffffffu, s, d);
            if (tid >= d) s += y;
        }
        if (tid < 16) wsum[tid] = s;
    }
    __syncthreads();
    int excl = (w ? wsum[w - 1] : 0) + incl - x;
    if (tid == 0) g_part[b] = wsum[15];
    gbar(2);

    // phase 2b: block 0 turns g_part into exclusive prefixes
    if (b == 0) {
        int v = (tid < GBLK) ? g_part[tid] : 0;
        if (tid < 256) sm2[tid] = v;
        __syncthreads();
        for (int d = 1; d < 256; d <<= 1) {
            int y = (tid < 256 && tid >= d) ? sm2[tid - d] : 0;
            __syncthreads();
            if (tid < 256) sm2[tid] += y;
            __syncthreads();
        }
        if (tid < GBLK) g_part[tid] = sm2[tid] - v;
    }
    gbar(3);

    // phase 2c: write offsets
    if (tid < SEG && idx <= N) {
        int o = excl + g_part[b];
        g_off[idx] = o;
        g_cur[idx] = o;
    }
    gbar(4);

    // phase 3: scatter
    for (int i = gt; i < quads; i += GT) {
        int4 d = ((const int4*)dst)[i];
        int p0 = atomicAdd(&g_cur[d.x], 1);
        int p1 = atomicAdd(&g_cur[d.y], 1);
        int p2 = atomicAdd(&g_cur[d.z], 1);
        int p3 = atomicAdd(&g_cur[d.w], 1);
        int e = 4 * i;
        g_eidx[p0] = e;
        g_eidx[p1] = e + 1;
        g_eidx[p2] = e + 2;
        g_eidx[p3] = e + 3;
    }
    if (gt < (E & 3)) {
        int e = (E & ~3) + gt;
        int p = atomicAdd(&g_cur[dst[e]], 1);
        g_eidx[p] = e;
    }
}

// ---------------------------------------------------------------------------
// ee table
// ---------------------------------------------------------------------------
__global__ void k_ee(const float* __restrict__ emb, const float* __restrict__ fce,
                     const float* __restrict__ attn_e) {
    int w = threadIdx.x >> 5;
    int lane = threadIdx.x & 31;
    if (w >= NET * H_) return;
    int et = w / H_, h = w % H_;
    float acc = 0.f;
    for (int f = lane; f < EF_; f += 32) {
        const float* row = fce + (h * EF_ + f) * EF_;
        float inner = 0.f;
#pragma unroll 8
        for (int k = 0; k < EF_; k++) inner += emb[et * EF_ + k] * row[k];
        acc += inner * attn_e[h * EF_ + f];
    }
#pragma unroll
    for (int d = 16; d; d >>= 1) acc += __shfl_xor_sync(0xffffffffu, acc, d);
    if (lane == 0) g_ee[et * H_ + h] = acc;
}

// ---------------------------------------------------------------------------
// k1: node transform + fused el/er (R10 version — best verified).
// ---------------------------------------------------------------------------
#define K1_SMEM_FLOATS (2 * T_ * DIN * 128 + T_ * DIN * PADN)  /* 56064 = 224256 B */
__global__ void __launch_bounds__(512) k1_transform(
    const float* __restrict__ feat, const float* __restrict__ fc,
    const float* __restrict__ resw, const float* __restrict__ attn_l,
    const float* __restrict__ attn_r, float* __restrict__ out, int N) {
    extern __shared__ float sh[];
    float* wf = sh;                          // [t*64+d][128]
    float* wr = sh + T_ * DIN * 128;
    float* sft = sh + 2 * T_ * DIN * 128;    // [t*64+d][PADN]
    for (int i = threadIdx.x; i < T_ * DIN * 128; i += blockDim.x) {
        wf[i] = fc[i];
        wr[i] = resw[i];
    }
    int lane = threadIdx.x & 31;
    int h = (threadIdx.x >> 5) & 3;          // head (column block of 32)
    int q = threadIdx.x >> 7;                // node quarter: 8 nodes
    int j = h * 32 + lane;                   // output column within 128
    int hb = h * 96 + lane;                  // output column in FDIM layout

    ull al2[T_], ar2[T_];
#pragma unroll
    for (int t = 0; t < T_; t++) {
        float a = attn_l[hb + t * 32];
        float b = attn_r[hb + t * 32];
        al2[t] = pack2(a, a);
        ar2[t] = pack2(b, b);
    }
    __syncthreads();

    for (int n0 = blockIdx.x * 32; n0 < N; n0 += gridDim.x * 32) {
        __syncthreads();
        int nNodes = min(32, N - n0);
        for (int i = threadIdx.x; i < 32 * 48; i += 512) {
            int n = i / 48, qq = i % 48;
            float4 v = (n < nNodes)
                ? __ldcs((const float4*)(feat + (size_t)(n0 + n) * FEAT_IN) + qq)
                : make_float4(0.f, 0.f, 0.f, 0.f);
            int k = qq * 4;
            sft[(k + 0) * PADN + n] = v.x;
            sft[(k + 1) * PADN + n] = v.y;
            sft[(k + 2) * PADN + n] = v.z;
            sft[(k + 3) * PADN + n] = v.w;
        }
        __syncthreads();

        ull elp[4], erp[4];
#pragma unroll
        for (int p = 0; p < 4; p++) { elp[p] = 0ull; erp[p] = 0ull; }

#pragma unroll
        for (int t = 0; t < T_; t++) {
            ull af[4], ar[4];
#pragma unroll
            for (int p = 0; p < 4; p++) { af[p] = 0ull; ar[p] = 0ull; }
            const float* wfp = wf + (t * DIN) * 128 + j;
            const float* wrp = wr + (t * DIN) * 128 + j;
            const float* fp = sft + (t * DIN) * PADN + q * 8;
#pragma unroll 8
            for (int d = 0; d < DIN; d++) {
                float ws = wfp[(size_t)d * 128];
                float rs = wrp[(size_t)d * 128];
                ull w2f = pack2(ws, ws);
                ull w2r = pack2(rs, rs);
                ulonglong2 fv01 = *(const ulonglong2*)(fp + d * PADN);
                ulonglong2 fv23 = *(const ulonglong2*)(fp + d * PADN + 4);
                af[0] = fma2(fv01.x, w2f, af[0]);
                ar[0] = fma2(fv01.x, w2r, ar[0]);
                af[1] = fma2(fv01.y, w2f, af[1]);
                ar[1] = fma2(fv01.y, w2r, ar[1]);
                af[2] = fma2(fv23.x, w2f, af[2]);
                ar[2] = fma2(fv23.x, w2r, ar[2]);
                af[3] = fma2(fv23.y, w2f, af[3]);
                ar[3] = fma2(fv23.y, w2r, ar[3]);
            }
            int c = hb + t * 32;
#pragma unroll
            for (int p = 0; p < 4; p++) {
                elp[p] = fma2(af[p], al2[t], elp[p]);
                erp[p] = fma2(af[p], ar2[t], erp[p]);
                int n = n0 + q * 8 + 2 * p;
                if (n < N) {
                    g_ft[(size_t)n * FDIM + c] = lo2(af[p]);
                    stcs32(out + (size_t)n * FDIM + c, lo2(ar[p]));
                }
                if (n + 1 < N) {
                    g_ft[(size_t)(n + 1) * FDIM + c] = hi2(af[p]);
                    stcs32(out + (size_t)(n + 1) * FDIM + c, hi2(ar[p]));
                }
            }
        }
#pragma unroll
        for (int p = 0; p < 4; p++) {
            float e0 = lo2(elp[p]), e1 = hi2(elp[p]);
            float r0 = lo2(erp[p]), r1 = hi2(erp[p]);
#pragma unroll
            for (int d = 16; d; d >>= 1) {
                e0 += __shfl_xor_sync(0xffffffffu, e0, d);
                e1 += __shfl_xor_sync(0xffffffffu, e1, d);
                r0 += __shfl_xor_sync(0xffffffffu, r0, d);
                r1 += __shfl_xor_sync(0xffffffffu, r1, d);
            }
            if (lane == 0) {
                int n = n0 + q * 8 + 2 * p;
                if (n < N) { g_el[n * 4 + h] = e0; g_er[n * 4 + h] = r0; }
                if (n + 1 < N) { g_el[(n + 1) * 4 + h] = e1; g_er[(n + 1) * 4 + h] = r1; }
            }
        }
    }
}

// ---------------------------------------------------------------------------
// k7: softmax + aggregation (verified R4/R10 config).
// ---------------------------------------------------------------------------
__global__ void __launch_bounds__(256) k7_agg(const int* __restrict__ src,
                                              const int* __restrict__ efeat,
                                              float* __restrict__ out, int N) {
    __shared__ int ssm[8][128];
    __shared__ float4 wsm[8][128];
    int wl = threadIdx.x >> 5;
    int n = (blockIdx.x * blockDim.x + threadIdx.x) >> 5;
    int lane = threadIdx.x & 31;
    if (n >= N) return;
    int s0 = g_off[n];
    int deg = g_off[n + 1] - s0;
    if (deg == 0) return;

    float4 er4 = *(const float4*)(g_er + n * 4);

    float4 vc[4];
    int sc[4];
    float4 m = make_float4(-1e30f, -1e30f, -1e30f, -1e30f);
#pragma unroll
    for (int c = 0; c < 4; c++) {
        int k = lane + 32 * c;
        sc[c] = 0;
        vc[c] = make_float4(0.f, 0.f, 0.f, 0.f);
        if (k < deg) {
            int e = g_eidx[s0 + k];
            int s = src[e];
            int et = efeat[e];
            float4 l4 = *(const float4*)(g_el + s * 4);
            float4 e4 = *(const float4*)(g_ee + et * 4);
            float4 v;
            v.x = lrelu(l4.x + er4.x + e4.x);
            v.y = lrelu(l4.y + er4.y + e4.y);
            v.z = lrelu(l4.z + er4.z + e4.z);
            v.w = lrelu(l4.w + er4.w + e4.w);
            sc[c] = s;
            vc[c] = v;
            m.x = fmaxf(m.x, v.x); m.y = fmaxf(m.y, v.y);
            m.z = fmaxf(m.z, v.z); m.w = fmaxf(m.w, v.w);
        }
    }
    for (int k = lane + 128; k < deg; k += 32) {
        int e = g_eidx[s0 + k];
        int s = src[e];
        int et = efeat[e];
        float4 l4 = *(const float4*)(g_el + s * 4);
        float4 e4 = *(const float4*)(g_ee + et * 4);
        m.x = fmaxf(m.x, lrelu(l4.x + er4.x + e4.x));
        m.y = fmaxf(m.y, lrelu(l4.y + er4.y + e4.y));
        m.z = fmaxf(m.z, lrelu(l4.z + er4.z + e4.z));
        m.w = fmaxf(m.w, lrelu(l4.w + er4.w + e4.w));
    }
#pragma unroll
    for (int d = 16; d; d >>= 1) {
        m.x = fmaxf(m.x, __shfl_xor_sync(0xffffffffu, m.x, d));
        m.y = fmaxf(m.y, __shfl_xor_sync(0xffffffffu, m.y, d));
        m.z = fmaxf(m.z, __shfl_xor_sync(0xffffffffu, m.z, d));
        m.w = fmaxf(m.w, __shfl_xor_sync(0xffffffffu, m.w, d));
    }

    float4 ss = make_float4(0.f, 0.f, 0.f, 0.f);
#pragma unroll
    for (int c = 0; c < 4; c++) {
        int k = lane + 32 * c;
        if (k < deg) {
            float4 ex;
            ex.x = __expf(vc[c].x - m.x);
            ex.y = __expf(vc[c].y - m.y);
            ex.z = __expf(vc[c].z - m.z);
            ex.w = __expf(vc[c].w - m.w);
            vc[c] = ex;
            ss.x += ex.x; ss.y += ex.y; ss.z += ex.z; ss.w += ex.w;
        }
    }
    for (int k = lane + 128; k < deg; k += 32) {
        int e = g_eidx[s0 + k];
        int s = src[e];
        int et = efeat[e];
        float4 l4 = *(const float4*)(g_el + s * 4);
        float4 e4 = *(const float4*)(g_ee + et * 4);
        ss.x += __expf(lrelu(l4.x + er4.x + e4.x) - m.x);
        ss.y += __expf(lrelu(l4.y + er4.y + e4.y) - m.y);
        ss.z += __expf(lrelu(l4.z + er4.z + e4.z) - m.z);
        ss.w += __expf(lrelu(l4.w + er4.w + e4.w) - m.w);
    }
#pragma unroll
    for (int d = 16; d; d >>= 1) {
        ss.x += __shfl_xor_sync(0xffffffffu, ss.x, d);
        ss.y += __shfl_xor_sync(0xffffffffu, ss.y, d);
        ss.z += __shfl_xor_sync(0xffffffffu, ss.z, d);
        ss.w += __shfl_xor_sync(0xffffffffu, ss.w, d);
    }
    float4 invd = make_float4(1.f / ss.x, 1.f / ss.y, 1.f / ss.z, 1.f / ss.w);

#pragma unroll
    for (int c = 0; c < 4; c++) {
        int k = lane + 32 * c;
        if (k < deg && k < 128) {
            ssm[wl][k] = sc[c];
            wsm[wl][k] = make_float4(vc[c].x * invd.x, vc[c].y * invd.y,
                                     vc[c].z * invd.z, vc[c].w * invd.w);
        }
    }
    __syncwarp();

    int h0 = (lane * 4) / 96;
    int h1 = (128 + lane * 4) / 96;
    int h2 = (256 + lane * 4) / 96;

    float4 a0 = make_float4(0.f, 0.f, 0.f, 0.f), a1 = a0, a2 = a0;
    int total = min(deg, 128);
    int k = 0;
    for (; k + 4 <= total; k += 4) {
        int s_[4];
        float4 w_[4];
#pragma unroll
        for (int u = 0; u < 4; u++) { s_[u] = ssm[wl][k + u]; w_[u] = wsm[wl][k + u]; }
        float4 p[4][3];
#pragma unroll
        for (int u = 0; u < 4; u++) {
            const float4* f4 = (const float4*)(g_ft + (size_t)s_[u] * FDIM);
            p[u][0] = f4[lane];
            p[u][1] = f4[32 + lane];
            p[u][2] = f4[64 + lane];
        }
#pragma unroll
        for (int u = 0; u < 4; u++) {
            float w0 = pick4(w_[u], h0), w1 = pick4(w_[u], h1), w2 = pick4(w_[u], h2);
            a0.x += p[u][0].x * w0; a0.y += p[u][0].y * w0; a0.z += p[u][0].z * w0; a0.w += p[u][0].w * w0;
            a1.x += p[u][1].x * w1; a1.y += p[u][1].y * w1; a1.z += p[u][1].z * w1; a1.w += p[u][1].w * w1;
            a2.x += p[u][2].x * w2; a2.y += p[u][2].y * w2; a2.z += p[u][2].z * w2; a2.w += p[u][2].w * w2;
        }
    }
    for (; k < total; k++) {
        int s = ssm[wl][k];
        float4 w4 = wsm[wl][k];
        float w0 = pick4(w4, h0), w1 = pick4(w4, h1), w2 = pick4(w4, h2);
        const float4* f4 = (const float4*)(g_ft + (size_t)s * FDIM);
        float4 p0 = f4[lane], p1 = f4[32 + lane], p2 = f4[64 + lane];
        a0.x += p0.x * w0; a0.y += p0.y * w0; a0.z += p0.z * w0; a0.w += p0.w * w0;
        a1.x += p1.x * w1; a1.y += p1.y * w1; a1.z += p1.z * w1; a1.w += p1.w * w1;
        a2.x += p2.x * w2; a2.y += p2.y * w2; a2.z += p2.z * w2; a2.w += p2.w * w2;
    }
    for (int kk = 128; kk < deg; kk++) {
        int e = g_eidx[s0 + kk];
        int s = src[e];
        int et = efeat[e];
        float4 l4 = *(const float4*)(g_el + s * 4);
        float4 e4 = *(const float4*)(g_ee + et * 4);
        float4 exv;
        exv.x = __expf(lrelu(l4.x + er4.x + e4.x) - m.x) * invd.x;
        exv.y = __expf(lrelu(l4.y + er4.y + e4.y) - m.y) * invd.y;
        exv.z = __expf(lrelu(l4.z + er4.z + e4.z) - m.z) * invd.z;
        exv.w = __expf(lrelu(l4.w + er4.w + e4.w) - m.w) * invd.w;
        float w0 = pick4(exv, h0), w1 = pick4(exv, h1), w2 = pick4(exv, h2);
        const float4* f4 = (const float4*)(g_ft + (size_t)s * FDIM);
        float4 p0 = f4[lane], p1 = f4[32 + lane], p2 = f4[64 + lane];
        a0.x += p0.x * w0; a0.y += p0.y * w0; a0.z += p0.z * w0; a0.w += p0.w * w0;
        a1.x += p1.x * w1; a1.y += p1.y * w1; a1.z += p1.z * w1; a1.w += p1.w * w1;
        a2.x += p2.x * w2; a2.y += p2.y * w2; a2.z += p2.z * w2; a2.w += p2.w * w2;
    }

    float4* o4 = (float4*)(out + (size_t)n * FDIM);
    float4 q;
    q = __ldcs(o4 + lane);
    q.x += a0.x; q.y += a0.y; q.z += a0.z; q.w += a0.w;
    __stcs(o4 + lane, q);
    q = __ldcs(o4 + 32 + lane);
    q.x += a1.x; q.y += a1.y; q.z += a1.z; q.w += a1.w;
    __stcs(o4 + 32 + lane, q);
    q = __ldcs(o4 + 64 + lane);
    q.x += a2.x; q.y += a2.y; q.z += a2.z; q.w += a2.w;
    __stcs(o4 + 64 + lane, q);
}

// ---------------------------------------------------------------------------
extern "C" void kernel_launch(void* const* d_in, const int* in_sizes, int n_in,
                              void* d_out, int out_size) {
    const float* feat   = (const float*)d_in[0];
    const int*   e_feat = (const int*)d_in[1];
    const int*   src    = (const int*)d_in[2];
    const int*   dst    = (const int*)d_in[3];
    const float* fc     = (const float*)d_in[4];
    const float* resw   = (const float*)d_in[5];
    const float* emb    = (const float*)d_in[6];
    const float* fce    = (const float*)d_in[7];
    const float* attn_l = (const float*)d_in[8];
    const float* attn_r = (const float*)d_in[9];
    const float* attn_e = (const float*)d_in[10];
    float* out = (float*)d_out;

    int N = in_sizes[0] / FEAT_IN;
    int E = in_sizes[1];

    cudaFuncSetAttribute(k1_transform, cudaFuncAttributeMaxDynamicSharedMemorySize,
                         K1_SMEM_FLOATS * (int)sizeof(float));

    // 4 launches; k7 lands in the profiler's capture slot (4th)
    k_csr<<<GBLK, GTHR>>>(dst, E, N);
    k_ee<<<1, 640>>>(emb, fce, attn_e);
    k1_transform<<<148, 512, K1_SMEM_FLOATS * (int)sizeof(float)>>>(
        feat, fc, resw, attn_l, attn_r, out, N);
    k7_agg<<<(N + 7) / 8, 256>>>(src, e_feat, out, N);
}

// round 12
// speedup vs baseline: 1.1521x; 1.1521x over previous
#include <cuda_runtime.h>

#define T_ 3
#define H_ 4
#define DIN 64
#define FEAT_IN 192     /* T_*DIN */
#define FDIM 384        /* H_ * T_*32 */
#define EF_ 64
#define NET 5
#define MAXN 50000
#define MAXE 400000
#define NEG_SLOPE 0.2f
#define PADN 36

typedef unsigned long long ull;

__device__ float g_ft[(size_t)MAXN * FDIM];
__device__ float g_el[MAXN * H_];
__device__ float g_er[MAXN * H_];
__device__ float g_ee[32];
__device__ int   g_cnt[MAXN + 1];
__device__ int   g_off[MAXN + 1];
__device__ int   g_cur[MAXN + 1];
__device__ int   g_eidx[MAXE];
__device__ int   g_part[256];

// side stream + events, created once at static-init (before harness checkpoints)
struct SideStream {
    cudaStream_t s;
    cudaEvent_t eFork, eJoin;
    SideStream() {
        cudaStreamCreateWithFlags(&s, cudaStreamNonBlocking);
        cudaEventCreateWithFlags(&eFork, cudaEventDisableTiming);
        cudaEventCreateWithFlags(&eJoin, cudaEventDisableTiming);
    }
};
static SideStream g_ss;

__device__ __forceinline__ ull pack2(float x, float y) {
    ull r; asm("mov.b64 %0, {%1,%2};" : "=l"(r) : "f"(x), "f"(y)); return r;
}
__device__ __forceinline__ ull fma2(ull a, ull b, ull c) {
    ull d; asm("fma.rn.f32x2 %0, %1, %2, %3;" : "=l"(d) : "l"(a), "l"(b), "l"(c)); return d;
}
__device__ __forceinline__ float lo2(ull v) { return __uint_as_float((unsigned)(v & 0xffffffffull)); }
__device__ __forceinline__ float hi2(ull v) { return __uint_as_float((unsigned)(v >> 32)); }
__device__ __forceinline__ void stcs32(float* p, float v) {
    asm volatile("st.global.cs.f32 [%0], %1;" :: "l"(p), "f"(v) : "memory");
}
__device__ __forceinline__ float lrelu(float x) { return x >= 0.f ? x : NEG_SLOPE * x; }
__device__ __forceinline__ float pick4(float4 v, int h) {
    float r = v.x;
    r = (h == 1) ? v.y : r;
    r = (h == 2) ? v.z : r;
    r = (h == 3) ? v.w : r;
    return r;
}

// ---------------------------------------------------------------------------
// CSR build (multi-kernel, verified R10 form)
// ---------------------------------------------------------------------------
__global__ void k_zero(int N) {
    int i = blockIdx.x * blockDim.x + threadIdx.x;
    if (i <= N) g_cnt[i] = 0;
}

__global__ void k_count(const int* __restrict__ dst, int E) {
    int i = blockIdx.x * blockDim.x + threadIdx.x;
    int base = i * 4;
    if (base + 3 < E) {
        int4 d = *(const int4*)(dst + base);
        atomicAdd(&g_cnt[d.x], 1);
        atomicAdd(&g_cnt[d.y], 1);
        atomicAdd(&g_cnt[d.z], 1);
        atomicAdd(&g_cnt[d.w], 1);
    } else {
        for (int e = base; e < E; e++) atomicAdd(&g_cnt[dst[e]], 1);
    }
}

__global__ void k_scan1(int N) {
    __shared__ int wsum[16];
    int t = threadIdx.x;
    int idx = blockIdx.x * 512 + t;
    int lane = t & 31, w = t >> 5;
    int x = (idx <= N) ? g_cnt[idx] : 0;
    int incl = x;
#pragma unroll
    for (int d = 1; d < 32; d <<= 1) {
        int y = __shfl_up_sync(0xffffffffu, incl, d);
        if (lane >= d) incl += y;
    }
    if (lane == 31) wsum[w] = incl;
    __syncthreads();
    if (t < 32) {
        int s = (t < 16) ? wsum[t] : 0;
#pragma unroll
        for (int d = 1; d < 16; d <<= 1) {
            int y = __shfl_up_sync(0xffffffffu, s, d);
            if (t >= d) s += y;
        }
        if (t < 16) wsum[t] = s;
    }
    __syncthreads();
    int excl = (w ? wsum[w - 1] : 0) + incl - x;
    if (idx <= N) g_off[idx] = excl;
    if (t == 0) g_part[blockIdx.x] = wsum[15];
}

__global__ void k_scan2(int P) {
    __shared__ int sm[256];
    int t = threadIdx.x;
    int v = (t < P) ? g_part[t] : 0;
    sm[t] = v;
    __syncthreads();
    for (int d = 1; d < 256; d <<= 1) {
        int y = (t >= d) ? sm[t - d] : 0;
        __syncthreads();
        sm[t] += y;
        __syncthreads();
    }
    if (t < P) g_part[t] = sm[t] - v;  // exclusive
}

__global__ void k_scan3(int N) {
    int idx = blockIdx.x * 512 + threadIdx.x;
    if (idx <= N) {
        int o = g_off[idx] + g_part[blockIdx.x];
        g_off[idx] = o;
        g_cur[idx] = o;
    }
}

__global__ void k_scatter(const int* __restrict__ dst, int E) {
    int i = blockIdx.x * blockDim.x + threadIdx.x;
    int base = i * 4;
    if (base + 3 < E) {
        int4 d = *(const int4*)(dst + base);
        int p0 = atomicAdd(&g_cur[d.x], 1);
        int p1 = atomicAdd(&g_cur[d.y], 1);
        int p2 = atomicAdd(&g_cur[d.z], 1);
        int p3 = atomicAdd(&g_cur[d.w], 1);
        g_eidx[p0] = base;
        g_eidx[p1] = base + 1;
        g_eidx[p2] = base + 2;
        g_eidx[p3] = base + 3;
    } else {
        for (int e = base; e < E; e++) {
            int p = atomicAdd(&g_cur[dst[e]], 1);
            g_eidx[p] = e;
        }
    }
}

// ---------------------------------------------------------------------------
// ee table
// ---------------------------------------------------------------------------
__global__ void k_ee(const float* __restrict__ emb, const float* __restrict__ fce,
                     const float* __restrict__ attn_e) {
    int w = threadIdx.x >> 5;
    int lane = threadIdx.x & 31;
    if (w >= NET * H_) return;
    int et = w / H_, h = w % H_;
    float acc = 0.f;
    for (int f = lane; f < EF_; f += 32) {
        const float* row = fce + (h * EF_ + f) * EF_;
        float inner = 0.f;
#pragma unroll 8
        for (int k = 0; k < EF_; k++) inner += emb[et * EF_ + k] * row[k];
        acc += inner * attn_e[h * EF_ + f];
    }
#pragma unroll
    for (int d = 16; d; d >>= 1) acc += __shfl_xor_sync(0xffffffffu, acc, d);
    if (lane == 0) g_ee[et * H_ + h] = acc;
}

// ---------------------------------------------------------------------------
// k1: node transform + fused el/er (R10 version — best verified).
// ---------------------------------------------------------------------------
#define K1_SMEM_FLOATS (2 * T_ * DIN * 128 + T_ * DIN * PADN)  /* 56064 = 224256 B */
__global__ void __launch_bounds__(512) k1_transform(
    const float* __restrict__ feat, const float* __restrict__ fc,
    const float* __restrict__ resw, const float* __restrict__ attn_l,
    const float* __restrict__ attn_r, float* __restrict__ out, int N) {
    extern __shared__ float sh[];
    float* wf = sh;                          // [t*64+d][128]
    float* wr = sh + T_ * DIN * 128;
    float* sft = sh + 2 * T_ * DIN * 128;    // [t*64+d][PADN]
    for (int i = threadIdx.x; i < T_ * DIN * 128; i += blockDim.x) {
        wf[i] = fc[i];
        wr[i] = resw[i];
    }
    int lane = threadIdx.x & 31;
    int h = (threadIdx.x >> 5) & 3;          // head (column block of 32)
    int q = threadIdx.x >> 7;                // node quarter: 8 nodes
    int j = h * 32 + lane;                   // output column within 128
    int hb = h * 96 + lane;                  // output column in FDIM layout

    ull al2[T_], ar2[T_];
#pragma unroll
    for (int t = 0; t < T_; t++) {
        float a = attn_l[hb + t * 32];
        float b = attn_r[hb + t * 32];
        al2[t] = pack2(a, a);
        ar2[t] = pack2(b, b);
    }
    __syncthreads();

    for (int n0 = blockIdx.x * 32; n0 < N; n0 += gridDim.x * 32) {
        __syncthreads();
        int nNodes = min(32, N - n0);
        for (int i = threadIdx.x; i < 32 * 48; i += 512) {
            int n = i / 48, qq = i % 48;
            float4 v = (n < nNodes)
                ? __ldcs((const float4*)(feat + (size_t)(n0 + n) * FEAT_IN) + qq)
                : make_float4(0.f, 0.f, 0.f, 0.f);
            int k = qq * 4;
            sft[(k + 0) * PADN + n] = v.x;
            sft[(k + 1) * PADN + n] = v.y;
            sft[(k + 2) * PADN + n] = v.z;
            sft[(k + 3) * PADN + n] = v.w;
        }
        __syncthreads();

        ull elp[4], erp[4];
#pragma unroll
        for (int p = 0; p < 4; p++) { elp[p] = 0ull; erp[p] = 0ull; }

#pragma unroll
        for (int t = 0; t < T_; t++) {
            ull af[4], ar[4];
#pragma unroll
            for (int p = 0; p < 4; p++) { af[p] = 0ull; ar[p] = 0ull; }
            const float* wfp = wf + (t * DIN) * 128 + j;
            const float* wrp = wr + (t * DIN) * 128 + j;
            const float* fp = sft + (t * DIN) * PADN + q * 8;
#pragma unroll 8
            for (int d = 0; d < DIN; d++) {
                float ws = wfp[(size_t)d * 128];
                float rs = wrp[(size_t)d * 128];
                ull w2f = pack2(ws, ws);
                ull w2r = pack2(rs, rs);
                ulonglong2 fv01 = *(const ulonglong2*)(fp + d * PADN);
                ulonglong2 fv23 = *(const ulonglong2*)(fp + d * PADN + 4);
                af[0] = fma2(fv01.x, w2f, af[0]);
                ar[0] = fma2(fv01.x, w2r, ar[0]);
                af[1] = fma2(fv01.y, w2f, af[1]);
                ar[1] = fma2(fv01.y, w2r, ar[1]);
                af[2] = fma2(fv23.x, w2f, af[2]);
                ar[2] = fma2(fv23.x, w2r, ar[2]);
                af[3] = fma2(fv23.y, w2f, af[3]);
                ar[3] = fma2(fv23.y, w2r, ar[3]);
            }
            int c = hb + t * 32;
#pragma unroll
            for (int p = 0; p < 4; p++) {
                elp[p] = fma2(af[p], al2[t], elp[p]);
                erp[p] = fma2(af[p], ar2[t], erp[p]);
                int n = n0 + q * 8 + 2 * p;
                if (n < N) {
                    g_ft[(size_t)n * FDIM + c] = lo2(af[p]);
                    stcs32(out + (size_t)n * FDIM + c, lo2(ar[p]));
                }
                if (n + 1 < N) {
                    g_ft[(size_t)(n + 1) * FDIM + c] = hi2(af[p]);
                    stcs32(out + (size_t)(n + 1) * FDIM + c, hi2(ar[p]));
                }
            }
        }
#pragma unroll
        for (int p = 0; p < 4; p++) {
            float e0 = lo2(elp[p]), e1 = hi2(elp[p]);
            float r0 = lo2(erp[p]), r1 = hi2(erp[p]);
#pragma unroll
            for (int d = 16; d; d >>= 1) {
                e0 += __shfl_xor_sync(0xffffffffu, e0, d);
                e1 += __shfl_xor_sync(0xffffffffu, e1, d);
                r0 += __shfl_xor_sync(0xffffffffu, r0, d);
                r1 += __shfl_xor_sync(0xffffffffu, r1, d);
            }
            if (lane == 0) {
                int n = n0 + q * 8 + 2 * p;
                if (n < N) { g_el[n * 4 + h] = e0; g_er[n * 4 + h] = r0; }
                if (n + 1 < N) { g_el[(n + 1) * 4 + h] = e1; g_er[(n + 1) * 4 + h] = r1; }
            }
        }
    }
}

// ---------------------------------------------------------------------------
// k7: softmax + aggregation (verified config).
// ---------------------------------------------------------------------------
__global__ void __launch_bounds__(256) k7_agg(const int* __restrict__ src,
                                              const int* __restrict__ efeat,
                                              float* __restrict__ out, int N) {
    __shared__ int ssm[8][128];
    __shared__ float4 wsm[8][128];
    int wl = threadIdx.x >> 5;
    int n = (blockIdx.x * blockDim.x + threadIdx.x) >> 5;
    int lane = threadIdx.x & 31;
    if (n >= N) return;
    int s0 = g_off[n];
    int deg = g_off[n + 1] - s0;
    if (deg == 0) return;

    float4 er4 = *(const float4*)(g_er + n * 4);

    float4 vc[4];
    int sc[4];
    float4 m = make_float4(-1e30f, -1e30f, -1e30f, -1e30f);
#pragma unroll
    for (int c = 0; c < 4; c++) {
        int k = lane + 32 * c;
        sc[c] = 0;
        vc[c] = make_float4(0.f, 0.f, 0.f, 0.f);
        if (k < deg) {
            int e = g_eidx[s0 + k];
            int s = src[e];
            int et = efeat[e];
            float4 l4 = *(const float4*)(g_el + s * 4);
            float4 e4 = *(const float4*)(g_ee + et * 4);
            float4 v;
            v.x = lrelu(l4.x + er4.x + e4.x);
            v.y = lrelu(l4.y + er4.y + e4.y);
            v.z = lrelu(l4.z + er4.z + e4.z);
            v.w = lrelu(l4.w + er4.w + e4.w);
            sc[c] = s;
            vc[c] = v;
            m.x = fmaxf(m.x, v.x); m.y = fmaxf(m.y, v.y);
            m.z = fmaxf(m.z, v.z); m.w = fmaxf(m.w, v.w);
        }
    }
    for (int k = lane + 128; k < deg; k += 32) {
        int e = g_eidx[s0 + k];
        int s = src[e];
        int et = efeat[e];
        float4 l4 = *(const float4*)(g_el + s * 4);
        float4 e4 = *(const float4*)(g_ee + et * 4);
        m.x = fmaxf(m.x, lrelu(l4.x + er4.x + e4.x));
        m.y = fmaxf(m.y, lrelu(l4.y + er4.y + e4.y));
        m.z = fmaxf(m.z, lrelu(l4.z + er4.z + e4.z));
        m.w = fmaxf(m.w, lrelu(l4.w + er4.w + e4.w));
    }
#pragma unroll
    for (int d = 16; d; d >>= 1) {
        m.x = fmaxf(m.x, __shfl_xor_sync(0xffffffffu, m.x, d));
        m.y = fmaxf(m.y, __shfl_xor_sync(0xffffffffu, m.y, d));
        m.z = fmaxf(m.z, __shfl_xor_sync(0xffffffffu, m.z, d));
        m.w = fmaxf(m.w, __shfl_xor_sync(0xffffffffu, m.w, d));
    }

    float4 ss = make_float4(0.f, 0.f, 0.f, 0.f);
#pragma unroll
    for (int c = 0; c < 4; c++) {
        int k = lane + 32 * c;
        if (k < deg) {
            float4 ex;
            ex.x = __expf(vc[c].x - m.x);
            ex.y = __expf(vc[c].y - m.y);
            ex.z = __expf(vc[c].z - m.z);
            ex.w = __expf(vc[c].w - m.w);
            vc[c] = ex;
            ss.x += ex.x; ss.y += ex.y; ss.z += ex.z; ss.w += ex.w;
        }
    }
    for (int k = lane + 128; k < deg; k += 32) {
        int e = g_eidx[s0 + k];
        int s = src[e];
        int et = efeat[e];
        float4 l4 = *(const float4*)(g_el + s * 4);
        float4 e4 = *(const float4*)(g_ee + et * 4);
        ss.x += __expf(lrelu(l4.x + er4.x + e4.x) - m.x);
        ss.y += __expf(lrelu(l4.y + er4.y + e4.y) - m.y);
        ss.z += __expf(lrelu(l4.z + er4.z + e4.z) - m.z);
        ss.w += __expf(lrelu(l4.w + er4.w + e4.w) - m.w);
    }
#pragma unroll
    for (int d = 16; d; d >>= 1) {
        ss.x += __shfl_xor_sync(0xffffffffu, ss.x, d);
        ss.y += __shfl_xor_sync(0xffffffffu, ss.y, d);
        ss.z += __shfl_xor_sync(0xffffffffu, ss.z, d);
        ss.w += __shfl_xor_sync(0xffffffffu, ss.w, d);
    }
    float4 invd = make_float4(1.f / ss.x, 1.f / ss.y, 1.f / ss.z, 1.f / ss.w);

#pragma unroll
    for (int c = 0; c < 4; c++) {
        int k = lane + 32 * c;
        if (k < deg && k < 128) {
            ssm[wl][k] = sc[c];
            wsm[wl][k] = make_float4(vc[c].x * invd.x, vc[c].y * invd.y,
                                     vc[c].z * invd.z, vc[c].w * invd.w);
        }
    }
    __syncwarp();

    int h0 = (lane * 4) / 96;
    int h1 = (128 + lane * 4) / 96;
    int h2 = (256 + lane * 4) / 96;

    float4 a0 = make_float4(0.f, 0.f, 0.f, 0.f), a1 = a0, a2 = a0;
    int total = min(deg, 128);
    int k = 0;
    for (; k + 4 <= total; k += 4) {
        int s_[4];
        float4 w_[4];
#pragma unroll
        for (int u = 0; u < 4; u++) { s_[u] = ssm[wl][k + u]; w_[u] = wsm[wl][k + u]; }
        float4 p[4][3];
#pragma unroll
        for (int u = 0; u < 4; u++) {
            const float4* f4 = (const float4*)(g_ft + (size_t)s_[u] * FDIM);
            p[u][0] = f4[lane];
            p[u][1] = f4[32 + lane];
            p[u][2] = f4[64 + lane];
        }
#pragma unroll
        for (int u = 0; u < 4; u++) {
            float w0 = pick4(w_[u], h0), w1 = pick4(w_[u], h1), w2 = pick4(w_[u], h2);
            a0.x += p[u][0].x * w0; a0.y += p[u][0].y * w0; a0.z += p[u][0].z * w0; a0.w += p[u][0].w * w0;
            a1.x += p[u][1].x * w1; a1.y += p[u][1].y * w1; a1.z += p[u][1].z * w1; a1.w += p[u][1].w * w1;
            a2.x += p[u][2].x * w2; a2.y += p[u][2].y * w2; a2.z += p[u][2].z * w2; a2.w += p[u][2].w * w2;
        }
    }
    for (; k < total; k++) {
        int s = ssm[wl][k];
        float4 w4 = wsm[wl][k];
        float w0 = pick4(w4, h0), w1 = pick4(w4, h1), w2 = pick4(w4, h2);
        const float4* f4 = (const float4*)(g_ft + (size_t)s * FDIM);
        float4 p0 = f4[lane], p1 = f4[32 + lane], p2 = f4[64 + lane];
        a0.x += p0.x * w0; a0.y += p0.y * w0; a0.z += p0.z * w0; a0.w += p0.w * w0;
        a1.x += p1.x * w1; a1.y += p1.y * w1; a1.z += p1.z * w1; a1.w += p1.w * w1;
        a2.x += p2.x * w2; a2.y += p2.y * w2; a2.z += p2.z * w2; a2.w += p2.w * w2;
    }
    for (int kk = 128; kk < deg; kk++) {
        int e = g_eidx[s0 + kk];
        int s = src[e];
        int et = efeat[e];
        float4 l4 = *(const float4*)(g_el + s * 4);
        float4 e4 = *(const float4*)(g_ee + et * 4);
        float4 exv;
        exv.x = __expf(lrelu(l4.x + er4.x + e4.x) - m.x) * invd.x;
        exv.y = __expf(lrelu(l4.y + er4.y + e4.y) - m.y) * invd.y;
        exv.z = __expf(lrelu(l4.z + er4.z + e4.z) - m.z) * invd.z;
        exv.w = __expf(lrelu(l4.w + er4.w + e4.w) - m.w) * invd.w;
        float w0 = pick4(exv, h0), w1 = pick4(exv, h1), w2 = pick4(exv, h2);
        const float4* f4 = (const float4*)(g_ft + (size_t)s * FDIM);
        float4 p0 = f4[lane], p1 = f4[32 + lane], p2 = f4[64 + lane];
        a0.x += p0.x * w0; a0.y += p0.y * w0; a0.z += p0.z * w0; a0.w += p0.w * w0;
        a1.x += p1.x * w1; a1.y += p1.y * w1; a1.z += p1.z * w1; a1.w += p1.w * w1;
        a2.x += p2.x * w2; a2.y += p2.y * w2; a2.z += p2.z * w2; a2.w += p2.w * w2;
    }

    float4* o4 = (float4*)(out + (size_t)n * FDIM);
    float4 q;
    q = __ldcs(o4 + lane);
    q.x += a0.x; q.y += a0.y; q.z += a0.z; q.w += a0.w;
    __stcs(o4 + lane, q);
    q = __ldcs(o4 + 32 + lane);
    q.x += a1.x; q.y += a1.y; q.z += a1.z; q.w += a1.w;
    __stcs(o4 + 32 + lane, q);
    q = __ldcs(o4 + 64 + lane);
    q.x += a2.x; q.y += a2.y; q.z += a2.z; q.w += a2.w;
    __stcs(o4 + 64 + lane, q);
}

// ---------------------------------------------------------------------------
extern "C" void kernel_launch(void* const* d_in, const int* in_sizes, int n_in,
                              void* d_out, int out_size) {
    const float* feat   = (const float*)d_in[0];
    const int*   e_feat = (const int*)d_in[1];
    const int*   src    = (const int*)d_in[2];
    const int*   dst    = (const int*)d_in[3];
    const float* fc     = (const float*)d_in[4];
    const float* resw   = (const float*)d_in[5];
    const float* emb    = (const float*)d_in[6];
    const float* fce    = (const float*)d_in[7];
    const float* attn_l = (const float*)d_in[8];
    const float* attn_r = (const float*)d_in[9];
    const float* attn_e = (const float*)d_in[10];
    float* out = (float*)d_out;

    int N = in_sizes[0] / FEAT_IN;
    int E = in_sizes[1];

    cudaFuncSetAttribute(k1_transform, cudaFuncAttributeMaxDynamicSharedMemorySize,
                         K1_SMEM_FLOATS * (int)sizeof(float));

    int scanBlocks = (N + 1 + 511) / 512;
    cudaStream_t s = g_ss.s;

    // fork: CSR chain + ee on side stream, overlapping k1 on the main stream
    cudaEventRecord(g_ss.eFork, 0);
    cudaStreamWaitEvent(s, g_ss.eFork, 0);

    k_zero<<<(N + 256) / 256, 256, 0, s>>>(N);
    k_count<<<(E / 4 + 255) / 256, 256, 0, s>>>(dst, E);
    k_scan1<<<scanBlocks, 512, 0, s>>>(N);
    k_scan2<<<1, 256, 0, s>>>(scanBlocks);
    k_scan3<<<scanBlocks, 512, 0, s>>>(N);
    k_scatter<<<(E / 4 + 255) / 256, 256, 0, s>>>(dst, E);
    k_ee<<<1, 640, 0, s>>>(emb, fce, attn_e);
    cudaEventRecord(g_ss.eJoin, s);

    // main stream: node transform (no CSR dependency)
    k1_transform<<<148, 512, K1_SMEM_FLOATS * (int)sizeof(float)>>>(
        feat, fc, resw, attn_l, attn_r, out, N);

    // join, then aggregation
    cudaStreamWaitEvent(0, g_ss.eJoin, 0);
    k7_agg<<<(N + 7) / 8, 256>>>(src, e_feat, out, N);
}

// round 13
// speedup vs baseline: 1.2425x; 1.0785x over previous
#include <cuda_runtime.h>

#define T_ 3
#define H_ 4
#define DIN 64
#define FEAT_IN 192     /* T_*DIN */
#define FDIM 384        /* H_ * T_*32 */
#define EF_ 64
#define NET 5
#define MAXN 50000
#define MAXE 400000
#define NEG_SLOPE 0.2f
#define PADN 36

typedef unsigned long long ull;

__device__ float g_ft[(size_t)MAXN * FDIM];
__device__ float g_el[MAXN * H_];
__device__ float g_er[MAXN * H_];
__device__ float g_ee[32];
__device__ int   g_cnt[MAXN + 1];
__device__ int   g_off[MAXN + 1];
__device__ int   g_cur[MAXN + 1];
__device__ int   g_eidx[MAXE];
__device__ int   g_part[256];

// side stream + events, created once at static-init (before harness checkpoints)
struct SideStream {
    cudaStream_t s;
    cudaEvent_t eFork, eJoin;
    SideStream() {
        cudaStreamCreateWithFlags(&s, cudaStreamNonBlocking);
        cudaEventCreateWithFlags(&eFork, cudaEventDisableTiming);
        cudaEventCreateWithFlags(&eJoin, cudaEventDisableTiming);
    }
};
static SideStream g_ss;

__device__ __forceinline__ ull pack2(float x, float y) {
    ull r; asm("mov.b64 %0, {%1,%2};" : "=l"(r) : "f"(x), "f"(y)); return r;
}
__device__ __forceinline__ ull fma2(ull a, ull b, ull c) {
    ull d; asm("fma.rn.f32x2 %0, %1, %2, %3;" : "=l"(d) : "l"(a), "l"(b), "l"(c)); return d;
}
__device__ __forceinline__ float lo2(ull v) { return __uint_as_float((unsigned)(v & 0xffffffffull)); }
__device__ __forceinline__ float hi2(ull v) { return __uint_as_float((unsigned)(v >> 32)); }
__device__ __forceinline__ void stcs32(float* p, float v) {
    asm volatile("st.global.cs.f32 [%0], %1;" :: "l"(p), "f"(v) : "memory");
}
__device__ __forceinline__ float lrelu(float x) { return x >= 0.f ? x : NEG_SLOPE * x; }
__device__ __forceinline__ float pick4(float4 v, int h) {
    float r = v.x;
    r = (h == 1) ? v.y : r;
    r = (h == 2) ? v.z : r;
    r = (h == 3) ? v.w : r;
    return r;
}

// ---------------------------------------------------------------------------
// CSR build (multi-kernel, verified form; runs on side stream under k1)
// ---------------------------------------------------------------------------
__global__ void k_zero(int N) {
    int i = blockIdx.x * blockDim.x + threadIdx.x;
    if (i <= N) g_cnt[i] = 0;
}

__global__ void k_count(const int* __restrict__ dst, int E) {
    int i = blockIdx.x * blockDim.x + threadIdx.x;
    int base = i * 4;
    if (base + 3 < E) {
        int4 d = *(const int4*)(dst + base);
        atomicAdd(&g_cnt[d.x], 1);
        atomicAdd(&g_cnt[d.y], 1);
        atomicAdd(&g_cnt[d.z], 1);
        atomicAdd(&g_cnt[d.w], 1);
    } else {
        for (int e = base; e < E; e++) atomicAdd(&g_cnt[dst[e]], 1);
    }
}

__global__ void k_scan1(int N) {
    __shared__ int wsum[16];
    int t = threadIdx.x;
    int idx = blockIdx.x * 512 + t;
    int lane = t & 31, w = t >> 5;
    int x = (idx <= N) ? g_cnt[idx] : 0;
    int incl = x;
#pragma unroll
    for (int d = 1; d < 32; d <<= 1) {
        int y = __shfl_up_sync(0xffffffffu, incl, d);
        if (lane >= d) incl += y;
    }
    if (lane == 31) wsum[w] = incl;
    __syncthreads();
    if (t < 32) {
        int s = (t < 16) ? wsum[t] : 0;
#pragma unroll
        for (int d = 1; d < 16; d <<= 1) {
            int y = __shfl_up_sync(0xffffffffu, s, d);
            if (t >= d) s += y;
        }
        if (t < 16) wsum[t] = s;
    }
    __syncthreads();
    int excl = (w ? wsum[w - 1] : 0) + incl - x;
    if (idx <= N) g_off[idx] = excl;
    if (t == 0) g_part[blockIdx.x] = wsum[15];
}

__global__ void k_scan2(int P) {
    __shared__ int sm[256];
    int t = threadIdx.x;
    int v = (t < P) ? g_part[t] : 0;
    sm[t] = v;
    __syncthreads();
    for (int d = 1; d < 256; d <<= 1) {
        int y = (t >= d) ? sm[t - d] : 0;
        __syncthreads();
        sm[t] += y;
        __syncthreads();
    }
    if (t < P) g_part[t] = sm[t] - v;  // exclusive
}

__global__ void k_scan3(int N) {
    int idx = blockIdx.x * 512 + threadIdx.x;
    if (idx <= N) {
        int o = g_off[idx] + g_part[blockIdx.x];
        g_off[idx] = o;
        g_cur[idx] = o;
    }
}

__global__ void k_scatter(const int* __restrict__ dst, int E) {
    int i = blockIdx.x * blockDim.x + threadIdx.x;
    int base = i * 4;
    if (base + 3 < E) {
        int4 d = *(const int4*)(dst + base);
        int p0 = atomicAdd(&g_cur[d.x], 1);
        int p1 = atomicAdd(&g_cur[d.y], 1);
        int p2 = atomicAdd(&g_cur[d.z], 1);
        int p3 = atomicAdd(&g_cur[d.w], 1);
        g_eidx[p0] = base;
        g_eidx[p1] = base + 1;
        g_eidx[p2] = base + 2;
        g_eidx[p3] = base + 3;
    } else {
        for (int e = base; e < E; e++) {
            int p = atomicAdd(&g_cur[dst[e]], 1);
            g_eidx[p] = e;
        }
    }
}

// ---------------------------------------------------------------------------
// ee table
// ---------------------------------------------------------------------------
__global__ void k_ee(const float* __restrict__ emb, const float* __restrict__ fce,
                     const float* __restrict__ attn_e) {
    int w = threadIdx.x >> 5;
    int lane = threadIdx.x & 31;
    if (w >= NET * H_) return;
    int et = w / H_, h = w % H_;
    float acc = 0.f;
    for (int f = lane; f < EF_; f += 32) {
        const float* row = fce + (h * EF_ + f) * EF_;
        float inner = 0.f;
#pragma unroll 8
        for (int k = 0; k < EF_; k++) inner += emb[et * EF_ + k] * row[k];
        acc += inner * attn_e[h * EF_ + f];
    }
#pragma unroll
    for (int d = 16; d; d >>= 1) acc += __shfl_xor_sync(0xffffffffu, acc, d);
    if (lane == 0) g_ee[et * H_ + h] = acc;
}

// ---------------------------------------------------------------------------
// k1: node transform + fused el/er (verified best).
// ---------------------------------------------------------------------------
#define K1_SMEM_FLOATS (2 * T_ * DIN * 128 + T_ * DIN * PADN)  /* 56064 = 224256 B */
__global__ void __launch_bounds__(512) k1_transform(
    const float* __restrict__ feat, const float* __restrict__ fc,
    const float* __restrict__ resw, const float* __restrict__ attn_l,
    const float* __restrict__ attn_r, float* __restrict__ out, int N) {
    extern __shared__ float sh[];
    float* wf = sh;                          // [t*64+d][128]
    float* wr = sh + T_ * DIN * 128;
    float* sft = sh + 2 * T_ * DIN * 128;    // [t*64+d][PADN]
    for (int i = threadIdx.x; i < T_ * DIN * 128; i += blockDim.x) {
        wf[i] = fc[i];
        wr[i] = resw[i];
    }
    int lane = threadIdx.x & 31;
    int h = (threadIdx.x >> 5) & 3;          // head (column block of 32)
    int q = threadIdx.x >> 7;                // node quarter: 8 nodes
    int j = h * 32 + lane;                   // output column within 128
    int hb = h * 96 + lane;                  // output column in FDIM layout

    ull al2[T_], ar2[T_];
#pragma unroll
    for (int t = 0; t < T_; t++) {
        float a = attn_l[hb + t * 32];
        float b = attn_r[hb + t * 32];
        al2[t] = pack2(a, a);
        ar2[t] = pack2(b, b);
    }
    __syncthreads();

    for (int n0 = blockIdx.x * 32; n0 < N; n0 += gridDim.x * 32) {
        __syncthreads();
        int nNodes = min(32, N - n0);
        for (int i = threadIdx.x; i < 32 * 48; i += 512) {
            int n = i / 48, qq = i % 48;
            float4 v = (n < nNodes)
                ? __ldcs((const float4*)(feat + (size_t)(n0 + n) * FEAT_IN) + qq)
                : make_float4(0.f, 0.f, 0.f, 0.f);
            int k = qq * 4;
            sft[(k + 0) * PADN + n] = v.x;
            sft[(k + 1) * PADN + n] = v.y;
            sft[(k + 2) * PADN + n] = v.z;
            sft[(k + 3) * PADN + n] = v.w;
        }
        __syncthreads();

        ull elp[4], erp[4];
#pragma unroll
        for (int p = 0; p < 4; p++) { elp[p] = 0ull; erp[p] = 0ull; }

#pragma unroll
        for (int t = 0; t < T_; t++) {
            ull af[4], ar[4];
#pragma unroll
            for (int p = 0; p < 4; p++) { af[p] = 0ull; ar[p] = 0ull; }
            const float* wfp = wf + (t * DIN) * 128 + j;
            const float* wrp = wr + (t * DIN) * 128 + j;
            const float* fp = sft + (t * DIN) * PADN + q * 8;
#pragma unroll 8
            for (int d = 0; d < DIN; d++) {
                float ws = wfp[(size_t)d * 128];
                float rs = wrp[(size_t)d * 128];
                ull w2f = pack2(ws, ws);
                ull w2r = pack2(rs, rs);
                ulonglong2 fv01 = *(const ulonglong2*)(fp + d * PADN);
                ulonglong2 fv23 = *(const ulonglong2*)(fp + d * PADN + 4);
                af[0] = fma2(fv01.x, w2f, af[0]);
                ar[0] = fma2(fv01.x, w2r, ar[0]);
                af[1] = fma2(fv01.y, w2f, af[1]);
                ar[1] = fma2(fv01.y, w2r, ar[1]);
                af[2] = fma2(fv23.x, w2f, af[2]);
                ar[2] = fma2(fv23.x, w2r, ar[2]);
                af[3] = fma2(fv23.y, w2f, af[3]);
                ar[3] = fma2(fv23.y, w2r, ar[3]);
            }
            int c = hb + t * 32;
#pragma unroll
            for (int p = 0; p < 4; p++) {
                elp[p] = fma2(af[p], al2[t], elp[p]);
                erp[p] = fma2(af[p], ar2[t], erp[p]);
                int n = n0 + q * 8 + 2 * p;
                if (n < N) {
                    g_ft[(size_t)n * FDIM + c] = lo2(af[p]);
                    stcs32(out + (size_t)n * FDIM + c, lo2(ar[p]));
                }
                if (n + 1 < N) {
                    g_ft[(size_t)(n + 1) * FDIM + c] = hi2(af[p]);
                    stcs32(out + (size_t)(n + 1) * FDIM + c, hi2(ar[p]));
                }
            }
        }
#pragma unroll
        for (int p = 0; p < 4; p++) {
            float e0 = lo2(elp[p]), e1 = hi2(elp[p]);
            float r0 = lo2(erp[p]), r1 = hi2(erp[p]);
#pragma unroll
            for (int d = 16; d; d >>= 1) {
                e0 += __shfl_xor_sync(0xffffffffu, e0, d);
                e1 += __shfl_xor_sync(0xffffffffu, e1, d);
                r0 += __shfl_xor_sync(0xffffffffu, r0, d);
                r1 += __shfl_xor_sync(0xffffffffu, r1, d);
            }
            if (lane == 0) {
                int n = n0 + q * 8 + 2 * p;
                if (n < N) { g_el[n * 4 + h] = e0; g_er[n * 4 + h] = r0; }
                if (n + 1 < N) { g_el[(n + 1) * 4 + h] = e1; g_er[(n + 1) * 4 + h] = r1; }
            }
        }
    }
}

// ---------------------------------------------------------------------------
// k7: softmax + aggregation. Reg-capped (<=64) for 4 blocks/SM; per-edge
// weights read from smem in the compute loop (shorter live ranges).
// ---------------------------------------------------------------------------
__global__ void __launch_bounds__(256, 4) k7_agg(const int* __restrict__ src,
                                                 const int* __restrict__ efeat,
                                                 float* __restrict__ out, int N) {
    __shared__ int ssm[8][128];
    __shared__ float4 wsm[8][128];
    int wl = threadIdx.x >> 5;
    int n = (blockIdx.x * blockDim.x + threadIdx.x) >> 5;
    int lane = threadIdx.x & 31;
    if (n >= N) return;
    int s0 = g_off[n];
    int deg = g_off[n + 1] - s0;
    if (deg == 0) return;

    float4 er4 = *(const float4*)(g_er + n * 4);

    float4 vc[4];
    int sc[4];
    float4 m = make_float4(-1e30f, -1e30f, -1e30f, -1e30f);
#pragma unroll
    for (int c = 0; c < 4; c++) {
        int k = lane + 32 * c;
        sc[c] = 0;
        vc[c] = make_float4(0.f, 0.f, 0.f, 0.f);
        if (k < deg) {
            int e = g_eidx[s0 + k];
            int s = src[e];
            int et = efeat[e];
            float4 l4 = *(const float4*)(g_el + s * 4);
            float4 e4 = *(const float4*)(g_ee + et * 4);
            float4 v;
            v.x = lrelu(l4.x + er4.x + e4.x);
            v.y = lrelu(l4.y + er4.y + e4.y);
            v.z = lrelu(l4.z + er4.z + e4.z);
            v.w = lrelu(l4.w + er4.w + e4.w);
            sc[c] = s;
            vc[c] = v;
            m.x = fmaxf(m.x, v.x); m.y = fmaxf(m.y, v.y);
            m.z = fmaxf(m.z, v.z); m.w = fmaxf(m.w, v.w);
        }
    }
    for (int k = lane + 128; k < deg; k += 32) {
        int e = g_eidx[s0 + k];
        int s = src[e];
        int et = efeat[e];
        float4 l4 = *(const float4*)(g_el + s * 4);
        float4 e4 = *(const float4*)(g_ee + et * 4);
        m.x = fmaxf(m.x, lrelu(l4.x + er4.x + e4.x));
        m.y = fmaxf(m.y, lrelu(l4.y + er4.y + e4.y));
        m.z = fmaxf(m.z, lrelu(l4.z + er4.z + e4.z));
        m.w = fmaxf(m.w, lrelu(l4.w + er4.w + e4.w));
    }
#pragma unroll
    for (int d = 16; d; d >>= 1) {
        m.x = fmaxf(m.x, __shfl_xor_sync(0xffffffffu, m.x, d));
        m.y = fmaxf(m.y, __shfl_xor_sync(0xffffffffu, m.y, d));
        m.z = fmaxf(m.z, __shfl_xor_sync(0xffffffffu, m.z, d));
        m.w = fmaxf(m.w, __shfl_xor_sync(0xffffffffu, m.w, d));
    }

    float4 ss = make_float4(0.f, 0.f, 0.f, 0.f);
#pragma unroll
    for (int c = 0; c < 4; c++) {
        int k = lane + 32 * c;
        if (k < deg) {
            float4 ex;
            ex.x = __expf(vc[c].x - m.x);
            ex.y = __expf(vc[c].y - m.y);
            ex.z = __expf(vc[c].z - m.z);
            ex.w = __expf(vc[c].w - m.w);
            vc[c] = ex;
            ss.x += ex.x; ss.y += ex.y; ss.z += ex.z; ss.w += ex.w;
        }
    }
    for (int k = lane + 128; k < deg; k += 32) {
        int e = g_eidx[s0 + k];
        int s = src[e];
        int et = efeat[e];
        float4 l4 = *(const float4*)(g_el + s * 4);
        float4 e4 = *(const float4*)(g_ee + et * 4);
        ss.x += __expf(lrelu(l4.x + er4.x + e4.x) - m.x);
        ss.y += __expf(lrelu(l4.y + er4.y + e4.y) - m.y);
        ss.z += __expf(lrelu(l4.z + er4.z + e4.z) - m.z);
        ss.w += __expf(lrelu(l4.w + er4.w + e4.w) - m.w);
    }
#pragma unroll
    for (int d = 16; d; d >>= 1) {
        ss.x += __shfl_xor_sync(0xffffffffu, ss.x, d);
        ss.y += __shfl_xor_sync(0xffffffffu, ss.y, d);
        ss.z += __shfl_xor_sync(0xffffffffu, ss.z, d);
        ss.w += __shfl_xor_sync(0xffffffffu, ss.w, d);
    }
    float4 invd = make_float4(1.f / ss.x, 1.f / ss.y, 1.f / ss.z, 1.f / ss.w);

#pragma unroll
    for (int c = 0; c < 4; c++) {
        int k = lane + 32 * c;
        if (k < deg && k < 128) {
            ssm[wl][k] = sc[c];
            wsm[wl][k] = make_float4(vc[c].x * invd.x, vc[c].y * invd.y,
                                     vc[c].z * invd.z, vc[c].w * invd.w);
        }
    }
    __syncwarp();

    int h0 = (lane * 4) / 96;
    int h1 = (128 + lane * 4) / 96;
    int h2 = (256 + lane * 4) / 96;

    float4 a0 = make_float4(0.f, 0.f, 0.f, 0.f), a1 = a0, a2 = a0;
    int total = min(deg, 128);
    int k = 0;
    for (; k + 4 <= total; k += 4) {
        int s_[4];
#pragma unroll
        for (int u = 0; u < 4; u++) s_[u] = ssm[wl][k + u];
        float4 p[4][3];
#pragma unroll
        for (int u = 0; u < 4; u++) {
            const float4* f4 = (const float4*)(g_ft + (size_t)s_[u] * FDIM);
            p[u][0] = f4[lane];
            p[u][1] = f4[32 + lane];
            p[u][2] = f4[64 + lane];
        }
#pragma unroll
        for (int u = 0; u < 4; u++) {
            float4 w4 = wsm[wl][k + u];
            float w0 = pick4(w4, h0), w1 = pick4(w4, h1), w2 = pick4(w4, h2);
            a0.x += p[u][0].x * w0; a0.y += p[u][0].y * w0; a0.z += p[u][0].z * w0; a0.w += p[u][0].w * w0;
            a1.x += p[u][1].x * w1; a1.y += p[u][1].y * w1; a1.z += p[u][1].z * w1; a1.w += p[u][1].w * w1;
            a2.x += p[u][2].x * w2; a2.y += p[u][2].y * w2; a2.z += p[u][2].z * w2; a2.w += p[u][2].w * w2;
        }
    }
    for (; k < total; k++) {
        int s = ssm[wl][k];
        float4 w4 = wsm[wl][k];
        float w0 = pick4(w4, h0), w1 = pick4(w4, h1), w2 = pick4(w4, h2);
        const float4* f4 = (const float4*)(g_ft + (size_t)s * FDIM);
        float4 p0 = f4[lane], p1 = f4[32 + lane], p2 = f4[64 + lane];
        a0.x += p0.x * w0; a0.y += p0.y * w0; a0.z += p0.z * w0; a0.w += p0.w * w0;
        a1.x += p1.x * w1; a1.y += p1.y * w1; a1.z += p1.z * w1; a1.w += p1.w * w1;
        a2.x += p2.x * w2; a2.y += p2.y * w2; a2.z += p2.z * w2; a2.w += p2.w * w2;
    }
    for (int kk = 128; kk < deg; kk++) {
        int e = g_eidx[s0 + kk];
        int s = src[e];
        int et = efeat[e];
        float4 l4 = *(const float4*)(g_el + s * 4);
        float4 e4 = *(const float4*)(g_ee + et * 4);
        float4 exv;
        exv.x = __expf(lrelu(l4.x + er4.x + e4.x) - m.x) * invd.x;
        exv.y = __expf(lrelu(l4.y + er4.y + e4.y) - m.y) * invd.y;
        exv.z = __expf(lrelu(l4.z + er4.z + e4.z) - m.z) * invd.z;
        exv.w = __expf(lrelu(l4.w + er4.w + e4.w) - m.w) * invd.w;
        float w0 = pick4(exv, h0), w1 = pick4(exv, h1), w2 = pick4(exv, h2);
        const float4* f4 = (const float4*)(g_ft + (size_t)s * FDIM);
        float4 p0 = f4[lane], p1 = f4[32 + lane], p2 = f4[64 + lane];
        a0.x += p0.x * w0; a0.y += p0.y * w0; a0.z += p0.z * w0; a0.w += p0.w * w0;
        a1.x += p1.x * w1; a1.y += p1.y * w1; a1.z += p1.z * w1; a1.w += p1.w * w1;
        a2.x += p2.x * w2; a2.y += p2.y * w2; a2.z += p2.z * w2; a2.w += p2.w * w2;
    }

    float4* o4 = (float4*)(out + (size_t)n * FDIM);
    float4 q;
    q = __ldcs(o4 + lane);
    q.x += a0.x; q.y += a0.y; q.z += a0.z; q.w += a0.w;
    __stcs(o4 + lane, q);
    q = __ldcs(o4 + 32 + lane);
    q.x += a1.x; q.y += a1.y; q.z += a1.z; q.w += a1.w;
    __stcs(o4 + 32 + lane, q);
    q = __ldcs(o4 + 64 + lane);
    q.x += a2.x; q.y += a2.y; q.z += a2.z; q.w += a2.w;
    __stcs(o4 + 64 + lane, q);
}

// ---------------------------------------------------------------------------
extern "C" void kernel_launch(void* const* d_in, const int* in_sizes, int n_in,
                              void* d_out, int out_size) {
    const float* feat   = (const float*)d_in[0];
    const int*   e_feat = (const int*)d_in[1];
    const int*   src    = (const int*)d_in[2];
    const int*   dst    = (const int*)d_in[3];
    const float* fc     = (const float*)d_in[4];
    const float* resw   = (const float*)d_in[5];
    const float* emb    = (const float*)d_in[6];
    const float* fce    = (const float*)d_in[7];
    const float* attn_l = (const float*)d_in[8];
    const float* attn_r = (const float*)d_in[9];
    const float* attn_e = (const float*)d_in[10];
    float* out = (float*)d_out;

    int N = in_sizes[0] / FEAT_IN;
    int E = in_sizes[1];

    cudaFuncSetAttribute(k1_transform, cudaFuncAttributeMaxDynamicSharedMemorySize,
                         K1_SMEM_FLOATS * (int)sizeof(float));

    int scanBlocks = (N + 1 + 511) / 512;
    cudaStream_t s = g_ss.s;

    // fork: CSR chain + ee on side stream, overlapping k1 on the main stream
    cudaEventRecord(g_ss.eFork, 0);
    cudaStreamWaitEvent(s, g_ss.eFork, 0);

    k_zero<<<(N + 256) / 256, 256, 0, s>>>(N);
    k_count<<<(E / 4 + 255) / 256, 256, 0, s>>>(dst, E);
    k_scan1<<<scanBlocks, 512, 0, s>>>(N);
    k_scan2<<<1, 256, 0, s>>>(scanBlocks);
    k_scan3<<<scanBlocks, 512, 0, s>>>(N);
    k_scatter<<<(E / 4 + 255) / 256, 256, 0, s>>>(dst, E);
    k_ee<<<1, 640, 0, s>>>(emb, fce, attn_e);
    cudaEventRecord(g_ss.eJoin, s);

    // main stream: node transform (no CSR dependency)
    k1_transform<<<148, 512, K1_SMEM_FLOATS * (int)sizeof(float)>>>(
        feat, fc, resw, attn_l, attn_r, out, N);

    // join, then aggregation
    cudaStreamWaitEvent(0, g_ss.eJoin, 0);
    k7_agg<<<(N + 7) / 8, 256>>>(src, e_feat, out, N);
}

// round 14
// speedup vs baseline: 1.2432x; 1.0005x over previous
#include <cuda_runtime.h>

#define T_ 3
#define H_ 4
#define DIN 64
#define FEAT_IN 192     /* T_*DIN */
#define FDIM 384        /* H_ * T_*32 */
#define EF_ 64
#define NET 5
#define MAXN 50000
#define MAXE 400000
#define NEG_SLOPE 0.2f
#define PADN 36

typedef unsigned long long ull;

__device__ float g_ft[(size_t)MAXN * FDIM];
__device__ float g_el[MAXN * H_];
__device__ float g_er[MAXN * H_];
__device__ float g_ee[32];
__device__ int   g_cnt[MAXN + 1];
__device__ int   g_off[MAXN + 1];
__device__ int   g_cur[MAXN + 1];
__device__ int   g_eidx[MAXE];
__device__ int   g_part[256];

// side stream + events, created once at static-init (before harness checkpoints)
struct SideStream {
    cudaStream_t s;
    cudaEvent_t eFork, eJoin;
    SideStream() {
        cudaStreamCreateWithFlags(&s, cudaStreamNonBlocking);
        cudaEventCreateWithFlags(&eFork, cudaEventDisableTiming);
        cudaEventCreateWithFlags(&eJoin, cudaEventDisableTiming);
    }
};
static SideStream g_ss;

__device__ __forceinline__ ull pack2(float x, float y) {
    ull r; asm("mov.b64 %0, {%1,%2};" : "=l"(r) : "f"(x), "f"(y)); return r;
}
__device__ __forceinline__ ull fma2(ull a, ull b, ull c) {
    ull d; asm("fma.rn.f32x2 %0, %1, %2, %3;" : "=l"(d) : "l"(a), "l"(b), "l"(c)); return d;
}
__device__ __forceinline__ float lo2(ull v) { return __uint_as_float((unsigned)(v & 0xffffffffull)); }
__device__ __forceinline__ float hi2(ull v) { return __uint_as_float((unsigned)(v >> 32)); }
__device__ __forceinline__ void stcs32(float* p, float v) {
    asm volatile("st.global.cs.f32 [%0], %1;" :: "l"(p), "f"(v) : "memory");
}
__device__ __forceinline__ float lrelu(float x) { return x >= 0.f ? x : NEG_SLOPE * x; }
__device__ __forceinline__ float pick4(float4 v, int h) {
    float r = v.x;
    r = (h == 1) ? v.y : r;
    r = (h == 2) ? v.z : r;
    r = (h == 3) ? v.w : r;
    return r;
}

// ---------------------------------------------------------------------------
// CSR build (multi-kernel, verified form; runs on side stream under k1)
// ---------------------------------------------------------------------------
__global__ void k_zero(int N) {
    int i = blockIdx.x * blockDim.x + threadIdx.x;
    if (i <= N) g_cnt[i] = 0;
}

__global__ void k_count(const int* __restrict__ dst, int E) {
    int i = blockIdx.x * blockDim.x + threadIdx.x;
    int base = i * 4;
    if (base + 3 < E) {
        int4 d = *(const int4*)(dst + base);
        atomicAdd(&g_cnt[d.x], 1);
        atomicAdd(&g_cnt[d.y], 1);
        atomicAdd(&g_cnt[d.z], 1);
        atomicAdd(&g_cnt[d.w], 1);
    } else {
        for (int e = base; e < E; e++) atomicAdd(&g_cnt[dst[e]], 1);
    }
}

__global__ void k_scan1(int N) {
    __shared__ int wsum[16];
    int t = threadIdx.x;
    int idx = blockIdx.x * 512 + t;
    int lane = t & 31, w = t >> 5;
    int x = (idx <= N) ? g_cnt[idx] : 0;
    int incl = x;
#pragma unroll
    for (int d = 1; d < 32; d <<= 1) {
        int y = __shfl_up_sync(0xffffffffu, incl, d);
        if (lane >= d) incl += y;
    }
    if (lane == 31) wsum[w] = incl;
    __syncthreads();
    if (t < 32) {
        int s = (t < 16) ? wsum[t] : 0;
#pragma unroll
        for (int d = 1; d < 16; d <<= 1) {
            int y = __shfl_up_sync(0xffffffffu, s, d);
            if (t >= d) s += y;
        }
        if (t < 16) wsum[t] = s;
    }
    __syncthreads();
    int excl = (w ? wsum[w - 1] : 0) + incl - x;
    if (idx <= N) g_off[idx] = excl;
    if (t == 0) g_part[blockIdx.x] = wsum[15];
}

__global__ void k_scan2(int P) {
    __shared__ int sm[256];
    int t = threadIdx.x;
    int v = (t < P) ? g_part[t] : 0;
    sm[t] = v;
    __syncthreads();
    for (int d = 1; d < 256; d <<= 1) {
        int y = (t >= d) ? sm[t - d] : 0;
        __syncthreads();
        sm[t] += y;
        __syncthreads();
    }
    if (t < P) g_part[t] = sm[t] - v;  // exclusive
}

__global__ void k_scan3(int N) {
    int idx = blockIdx.x * 512 + threadIdx.x;
    if (idx <= N) {
        int o = g_off[idx] + g_part[blockIdx.x];
        g_off[idx] = o;
        g_cur[idx] = o;
    }
}

__global__ void k_scatter(const int* __restrict__ dst, int E) {
    int i = blockIdx.x * blockDim.x + threadIdx.x;
    int base = i * 4;
    if (base + 3 < E) {
        int4 d = *(const int4*)(dst + base);
        int p0 = atomicAdd(&g_cur[d.x], 1);
        int p1 = atomicAdd(&g_cur[d.y], 1);
        int p2 = atomicAdd(&g_cur[d.z], 1);
        int p3 = atomicAdd(&g_cur[d.w], 1);
        g_eidx[p0] = base;
        g_eidx[p1] = base + 1;
        g_eidx[p2] = base + 2;
        g_eidx[p3] = base + 3;
    } else {
        for (int e = base; e < E; e++) {
            int p = atomicAdd(&g_cur[dst[e]], 1);
            g_eidx[p] = e;
        }
    }
}

// ---------------------------------------------------------------------------
// ee table
// ---------------------------------------------------------------------------
__global__ void k_ee(const float* __restrict__ emb, const float* __restrict__ fce,
                     const float* __restrict__ attn_e) {
    int w = threadIdx.x >> 5;
    int lane = threadIdx.x & 31;
    if (w >= NET * H_) return;
    int et = w / H_, h = w % H_;
    float acc = 0.f;
    for (int f = lane; f < EF_; f += 32) {
        const float* row = fce + (h * EF_ + f) * EF_;
        float inner = 0.f;
#pragma unroll 8
        for (int k = 0; k < EF_; k++) inner += emb[et * EF_ + k] * row[k];
        acc += inner * attn_e[h * EF_ + f];
    }
#pragma unroll
    for (int d = 16; d; d >>= 1) acc += __shfl_xor_sync(0xffffffffu, acc, d);
    if (lane == 0) g_ee[et * H_ + h] = acc;
}

// ---------------------------------------------------------------------------
// k1: node transform + fused el/er, with register-prefetch double buffering
// of the feat tile (hides tile LDG latency under compute).
// ---------------------------------------------------------------------------
#define K1_SMEM_FLOATS (2 * T_ * DIN * 128 + T_ * DIN * PADN)  /* 56064 = 224256 B */
__global__ void __launch_bounds__(512) k1_transform(
    const float* __restrict__ feat, const float* __restrict__ fc,
    const float* __restrict__ resw, const float* __restrict__ attn_l,
    const float* __restrict__ attn_r, float* __restrict__ out, int N) {
    extern __shared__ float sh[];
    float* wf = sh;                          // [t*64+d][128]
    float* wr = sh + T_ * DIN * 128;
    float* sft = sh + 2 * T_ * DIN * 128;    // [t*64+d][PADN]
    for (int i = threadIdx.x; i < T_ * DIN * 128; i += blockDim.x) {
        wf[i] = fc[i];
        wr[i] = resw[i];
    }
    int lane = threadIdx.x & 31;
    int h = (threadIdx.x >> 5) & 3;          // head (column block of 32)
    int q = threadIdx.x >> 7;                // node quarter: 8 nodes
    int j = h * 32 + lane;                   // output column within 128
    int hb = h * 96 + lane;                  // output column in FDIM layout

    // per-thread tile-load coordinates (3 float4 per thread: 32*48 = 512*3)
    int ln[3], lq[3];
#pragma unroll
    for (int k = 0; k < 3; k++) {
        int i = threadIdx.x + k * 512;
        ln[k] = i / 48;
        lq[k] = i % 48;
    }

    ull al2[T_], ar2[T_];
#pragma unroll
    for (int t = 0; t < T_; t++) {
        float a = attn_l[hb + t * 32];
        float b = attn_r[hb + t * 32];
        al2[t] = pack2(a, a);
        ar2[t] = pack2(b, b);
    }

    int step = gridDim.x * 32;
    int n0 = blockIdx.x * 32;

    // prefetch first tile into registers
    float4 pre[3];
#pragma unroll
    for (int k = 0; k < 3; k++) {
        int n = n0 + ln[k];
        pre[k] = (n < N)
            ? __ldcs((const float4*)(feat + (size_t)n * FEAT_IN) + lq[k])
            : make_float4(0.f, 0.f, 0.f, 0.f);
    }
    __syncthreads();

    for (; n0 < N; n0 += step) {
        __syncthreads();   // previous compute done reading sft
#pragma unroll
        for (int k = 0; k < 3; k++) {
            int kk = lq[k] * 4;
            sft[(kk + 0) * PADN + ln[k]] = pre[k].x;
            sft[(kk + 1) * PADN + ln[k]] = pre[k].y;
            sft[(kk + 2) * PADN + ln[k]] = pre[k].z;
            sft[(kk + 3) * PADN + ln[k]] = pre[k].w;
        }
        __syncthreads();

        // prefetch next tile (latency overlapped with compute below)
        int n1 = n0 + step;
        if (n1 < N) {
#pragma unroll
            for (int k = 0; k < 3; k++) {
                int n = n1 + ln[k];
                pre[k] = (n < N)
                    ? __ldcs((const float4*)(feat + (size_t)n * FEAT_IN) + lq[k])
                    : make_float4(0.f, 0.f, 0.f, 0.f);
            }
        }

        ull elp[4], erp[4];
#pragma unroll
        for (int p = 0; p < 4; p++) { elp[p] = 0ull; erp[p] = 0ull; }

#pragma unroll
        for (int t = 0; t < T_; t++) {
            ull af[4], ar[4];
#pragma unroll
            for (int p = 0; p < 4; p++) { af[p] = 0ull; ar[p] = 0ull; }
            const float* wfp = wf + (t * DIN) * 128 + j;
            const float* wrp = wr + (t * DIN) * 128 + j;
            const float* fp = sft + (t * DIN) * PADN + q * 8;
#pragma unroll 8
            for (int d = 0; d < DIN; d++) {
                float ws = wfp[(size_t)d * 128];
                float rs = wrp[(size_t)d * 128];
                ull w2f = pack2(ws, ws);
                ull w2r = pack2(rs, rs);
                ulonglong2 fv01 = *(const ulonglong2*)(fp + d * PADN);
                ulonglong2 fv23 = *(const ulonglong2*)(fp + d * PADN + 4);
                af[0] = fma2(fv01.x, w2f, af[0]);
                ar[0] = fma2(fv01.x, w2r, ar[0]);
                af[1] = fma2(fv01.y, w2f, af[1]);
                ar[1] = fma2(fv01.y, w2r, ar[1]);
                af[2] = fma2(fv23.x, w2f, af[2]);
                ar[2] = fma2(fv23.x, w2r, ar[2]);
                af[3] = fma2(fv23.y, w2f, af[3]);
                ar[3] = fma2(fv23.y, w2r, ar[3]);
            }
            int c = hb + t * 32;
#pragma unroll
            for (int p = 0; p < 4; p++) {
                elp[p] = fma2(af[p], al2[t], elp[p]);
                erp[p] = fma2(af[p], ar2[t], erp[p]);
                int n = n0 + q * 8 + 2 * p;
                if (n < N) {
                    g_ft[(size_t)n * FDIM + c] = lo2(af[p]);
                    stcs32(out + (size_t)n * FDIM + c, lo2(ar[p]));
                }
                if (n + 1 < N) {
                    g_ft[(size_t)(n + 1) * FDIM + c] = hi2(af[p]);
                    stcs32(out + (size_t)(n + 1) * FDIM + c, hi2(ar[p]));
                }
            }
        }
#pragma unroll
        for (int p = 0; p < 4; p++) {
            float e0 = lo2(elp[p]), e1 = hi2(elp[p]);
            float r0 = lo2(erp[p]), r1 = hi2(erp[p]);
#pragma unroll
            for (int d = 16; d; d >>= 1) {
                e0 += __shfl_xor_sync(0xffffffffu, e0, d);
                e1 += __shfl_xor_sync(0xffffffffu, e1, d);
                r0 += __shfl_xor_sync(0xffffffffu, r0, d);
                r1 += __shfl_xor_sync(0xffffffffu, r1, d);
            }
            if (lane == 0) {
                int n = n0 + q * 8 + 2 * p;
                if (n < N) { g_el[n * 4 + h] = e0; g_er[n * 4 + h] = r0; }
                if (n + 1 < N) { g_el[(n + 1) * 4 + h] = e1; g_er[(n + 1) * 4 + h] = r1; }
            }
        }
    }
}

// ---------------------------------------------------------------------------
// k7: softmax + aggregation (verified R13 config: reg-capped, smem weights).
// ---------------------------------------------------------------------------
__global__ void __launch_bounds__(256, 4) k7_agg(const int* __restrict__ src,
                                                 const int* __restrict__ efeat,
                                                 float* __restrict__ out, int N) {
    __shared__ int ssm[8][128];
    __shared__ float4 wsm[8][128];
    int wl = threadIdx.x >> 5;
    int n = (blockIdx.x * blockDim.x + threadIdx.x) >> 5;
    int lane = threadIdx.x & 31;
    if (n >= N) return;
    int s0 = g_off[n];
    int deg = g_off[n + 1] - s0;
    if (deg == 0) return;

    float4 er4 = *(const float4*)(g_er + n * 4);

    float4 vc[4];
    int sc[4];
    float4 m = make_float4(-1e30f, -1e30f, -1e30f, -1e30f);
#pragma unroll
    for (int c = 0; c < 4; c++) {
        int k = lane + 32 * c;
        sc[c] = 0;
        vc[c] = make_float4(0.f, 0.f, 0.f, 0.f);
        if (k < deg) {
            int e = g_eidx[s0 + k];
            int s = src[e];
            int et = efeat[e];
            float4 l4 = *(const float4*)(g_el + s * 4);
            float4 e4 = *(const float4*)(g_ee + et * 4);
            float4 v;
            v.x = lrelu(l4.x + er4.x + e4.x);
            v.y = lrelu(l4.y + er4.y + e4.y);
            v.z = lrelu(l4.z + er4.z + e4.z);
            v.w = lrelu(l4.w + er4.w + e4.w);
            sc[c] = s;
            vc[c] = v;
            m.x = fmaxf(m.x, v.x); m.y = fmaxf(m.y, v.y);
            m.z = fmaxf(m.z, v.z); m.w = fmaxf(m.w, v.w);
        }
    }
    for (int k = lane + 128; k < deg; k += 32) {
        int e = g_eidx[s0 + k];
        int s = src[e];
        int et = efeat[e];
        float4 l4 = *(const float4*)(g_el + s * 4);
        float4 e4 = *(const float4*)(g_ee + et * 4);
        m.x = fmaxf(m.x, lrelu(l4.x + er4.x + e4.x));
        m.y = fmaxf(m.y, lrelu(l4.y + er4.y + e4.y));
        m.z = fmaxf(m.z, lrelu(l4.z + er4.z + e4.z));
        m.w = fmaxf(m.w, lrelu(l4.w + er4.w + e4.w));
    }
#pragma unroll
    for (int d = 16; d; d >>= 1) {
        m.x = fmaxf(m.x, __shfl_xor_sync(0xffffffffu, m.x, d));
        m.y = fmaxf(m.y, __shfl_xor_sync(0xffffffffu, m.y, d));
        m.z = fmaxf(m.z, __shfl_xor_sync(0xffffffffu, m.z, d));
        m.w = fmaxf(m.w, __shfl_xor_sync(0xffffffffu, m.w, d));
    }

    float4 ss = make_float4(0.f, 0.f, 0.f, 0.f);
#pragma unroll
    for (int c = 0; c < 4; c++) {
        int k = lane + 32 * c;
        if (k < deg) {
            float4 ex;
            ex.x = __expf(vc[c].x - m.x);
            ex.y = __expf(vc[c].y - m.y);
            ex.z = __expf(vc[c].z - m.z);
            ex.w = __expf(vc[c].w - m.w);
            vc[c] = ex;
            ss.x += ex.x; ss.y += ex.y; ss.z += ex.z; ss.w += ex.w;
        }
    }
    for (int k = lane + 128; k < deg; k += 32) {
        int e = g_eidx[s0 + k];
        int s = src[e];
        int et = efeat[e];
        float4 l4 = *(const float4*)(g_el + s * 4);
        float4 e4 = *(const float4*)(g_ee + et * 4);
        ss.x += __expf(lrelu(l4.x + er4.x + e4.x) - m.x);
        ss.y += __expf(lrelu(l4.y + er4.y + e4.y) - m.y);
        ss.z += __expf(lrelu(l4.z + er4.z + e4.z) - m.z);
        ss.w += __expf(lrelu(l4.w + er4.w + e4.w) - m.w);
    }
#pragma unroll
    for (int d = 16; d; d >>= 1) {
        ss.x += __shfl_xor_sync(0xffffffffu, ss.x, d);
        ss.y += __shfl_xor_sync(0xffffffffu, ss.y, d);
        ss.z += __shfl_xor_sync(0xffffffffu, ss.z, d);
        ss.w += __shfl_xor_sync(0xffffffffu, ss.w, d);
    }
    float4 invd = make_float4(1.f / ss.x, 1.f / ss.y, 1.f / ss.z, 1.f / ss.w);

#pragma unroll
    for (int c = 0; c < 4; c++) {
        int k = lane + 32 * c;
        if (k < deg && k < 128) {
            ssm[wl][k] = sc[c];
            wsm[wl][k] = make_float4(vc[c].x * invd.x, vc[c].y * invd.y,
                                     vc[c].z * invd.z, vc[c].w * invd.w);
        }
    }
    __syncwarp();

    int h0 = (lane * 4) / 96;
    int h1 = (128 + lane * 4) / 96;
    int h2 = (256 + lane * 4) / 96;

    float4 a0 = make_float4(0.f, 0.f, 0.f, 0.f), a1 = a0, a2 = a0;
    int total = min(deg, 128);
    int k = 0;
    for (; k + 4 <= total; k += 4) {
        int s_[4];
#pragma unroll
        for (int u = 0; u < 4; u++) s_[u] = ssm[wl][k + u];
        float4 p[4][3];
#pragma unroll
        for (int u = 0; u < 4; u++) {
            const float4* f4 = (const float4*)(g_ft + (size_t)s_[u] * FDIM);
            p[u][0] = f4[lane];
            p[u][1] = f4[32 + lane];
            p[u][2] = f4[64 + lane];
        }
#pragma unroll
        for (int u = 0; u < 4; u++) {
            float4 w4 = wsm[wl][k + u];
            float w0 = pick4(w4, h0), w1 = pick4(w4, h1), w2 = pick4(w4, h2);
            a0.x += p[u][0].x * w0; a0.y += p[u][0].y * w0; a0.z += p[u][0].z * w0; a0.w += p[u][0].w * w0;
            a1.x += p[u][1].x * w1; a1.y += p[u][1].y * w1; a1.z += p[u][1].z * w1; a1.w += p[u][1].w * w1;
            a2.x += p[u][2].x * w2; a2.y += p[u][2].y * w2; a2.z += p[u][2].z * w2; a2.w += p[u][2].w * w2;
        }
    }
    for (; k < total; k++) {
        int s = ssm[wl][k];
        float4 w4 = wsm[wl][k];
        float w0 = pick4(w4, h0), w1 = pick4(w4, h1), w2 = pick4(w4, h2);
        const float4* f4 = (const float4*)(g_ft + (size_t)s * FDIM);
        float4 p0 = f4[lane], p1 = f4[32 + lane], p2 = f4[64 + lane];
        a0.x += p0.x * w0; a0.y += p0.y * w0; a0.z += p0.z * w0; a0.w += p0.w * w0;
        a1.x += p1.x * w1; a1.y += p1.y * w1; a1.z += p1.z * w1; a1.w += p1.w * w1;
        a2.x += p2.x * w2; a2.y += p2.y * w2; a2.z += p2.z * w2; a2.w += p2.w * w2;
    }
    for (int kk = 128; kk < deg; kk++) {
        int e = g_eidx[s0 + kk];
        int s = src[e];
        int et = efeat[e];
        float4 l4 = *(const float4*)(g_el + s * 4);
        float4 e4 = *(const float4*)(g_ee + et * 4);
        float4 exv;
        exv.x = __expf(lrelu(l4.x + er4.x + e4.x) - m.x) * invd.x;
        exv.y = __expf(lrelu(l4.y + er4.y + e4.y) - m.y) * invd.y;
        exv.z = __expf(lrelu(l4.z + er4.z + e4.z) - m.z) * invd.z;
        exv.w = __expf(lrelu(l4.w + er4.w + e4.w) - m.w) * invd.w;
        float w0 = pick4(exv, h0), w1 = pick4(exv, h1), w2 = pick4(exv, h2);
        const float4* f4 = (const float4*)(g_ft + (size_t)s * FDIM);
        float4 p0 = f4[lane], p1 = f4[32 + lane], p2 = f4[64 + lane];
        a0.x += p0.x * w0; a0.y += p0.y * w0; a0.z += p0.z * w0; a0.w += p0.w * w0;
        a1.x += p1.x * w1; a1.y += p1.y * w1; a1.z += p1.z * w1; a1.w += p1.w * w1;
        a2.x += p2.x * w2; a2.y += p2.y * w2; a2.z += p2.z * w2; a2.w += p2.w * w2;
    }

    float4* o4 = (float4*)(out + (size_t)n * FDIM);
    float4 q;
    q = __ldcs(o4 + lane);
    q.x += a0.x; q.y += a0.y; q.z += a0.z; q.w += a0.w;
    __stcs(o4 + lane, q);
    q = __ldcs(o4 + 32 + lane);
    q.x += a1.x; q.y += a1.y; q.z += a1.z; q.w += a1.w;
    __stcs(o4 + 32 + lane, q);
    q = __ldcs(o4 + 64 + lane);
    q.x += a2.x; q.y += a2.y; q.z += a2.z; q.w += a2.w;
    __stcs(o4 + 64 + lane, q);
}

// ---------------------------------------------------------------------------
extern "C" void kernel_launch(void* const* d_in, const int* in_sizes, int n_in,
                              void* d_out, int out_size) {
    const float* feat   = (const float*)d_in[0];
    const int*   e_feat = (const int*)d_in[1];
    const int*   src    = (const int*)d_in[2];
    const int*   dst    = (const int*)d_in[3];
    const float* fc     = (const float*)d_in[4];
    const float* resw   = (const float*)d_in[5];
    const float* emb    = (const float*)d_in[6];
    const float* fce    = (const float*)d_in[7];
    const float* attn_l = (const float*)d_in[8];
    const float* attn_r = (const float*)d_in[9];
    const float* attn_e = (const float*)d_in[10];
    float* out = (float*)d_out;

    int N = in_sizes[0] / FEAT_IN;
    int E = in_sizes[1];

    cudaFuncSetAttribute(k1_transform, cudaFuncAttributeMaxDynamicSharedMemorySize,
                         K1_SMEM_FLOATS * (int)sizeof(float));

    int scanBlocks = (N + 1 + 511) / 512;
    cudaStream_t s = g_ss.s;

    // fork: CSR chain + ee on side stream, overlapping k1 on the main stream
    cudaEventRecord(g_ss.eFork, 0);
    cudaStreamWaitEvent(s, g_ss.eFork, 0);

    k_zero<<<(N + 256) / 256, 256, 0, s>>>(N);
    k_count<<<(E / 4 + 255) / 256, 256, 0, s>>>(dst, E);
    k_scan1<<<scanBlocks, 512, 0, s>>>(N);
    k_scan2<<<1, 256, 0, s>>>(scanBlocks);
    k_scan3<<<scanBlocks, 512, 0, s>>>(N);
    k_scatter<<<(E / 4 + 255) / 256, 256, 0, s>>>(dst, E);
    k_ee<<<1, 640, 0, s>>>(emb, fce, attn_e);
    cudaEventRecord(g_ss.eJoin, s);

    // main stream: node transform (no CSR dependency)
    k1_transform<<<148, 512, K1_SMEM_FLOATS * (int)sizeof(float)>>>(
        feat, fc, resw, attn_l, attn_r, out, N);

    // join, then aggregation
    cudaStreamWaitEvent(0, g_ss.eJoin, 0);
    k7_agg<<<(N + 7) / 8, 256>>>(src, e_feat, out, N);
}

// round 15
// speedup vs baseline: 1.2706x; 1.0220x over previous
#include <cuda_runtime.h>

#define T_ 3
#define H_ 4
#define DIN 64
#define FEAT_IN 192     /* T_*DIN */
#define FDIM 384        /* H_ * T_*32 */
#define EF_ 64
#define NET 5
#define MAXN 50000
#define MAXE 400000
#define NEG_SLOPE 0.2f
#define PADN 36

typedef unsigned long long ull;

__device__ float g_ft[(size_t)MAXN * FDIM];
__device__ float g_el[MAXN * H_];
__device__ float g_er[MAXN * H_];
__device__ float g_ee[32];
__device__ int   g_cnt[MAXN + 1];
__device__ int   g_off[MAXN + 1];
__device__ int   g_cur[MAXN + 1];
__device__ int2  g_edge[MAXE];   // CSR payload: {src, etype}
__device__ int   g_part[256];

// side stream + events, created once at static-init (before harness checkpoints)
struct SideStream {
    cudaStream_t s;
    cudaEvent_t eFork, eJoin;
    SideStream() {
        cudaStreamCreateWithFlags(&s, cudaStreamNonBlocking);
        cudaEventCreateWithFlags(&eFork, cudaEventDisableTiming);
        cudaEventCreateWithFlags(&eJoin, cudaEventDisableTiming);
    }
};
static SideStream g_ss;

__device__ __forceinline__ ull pack2(float x, float y) {
    ull r; asm("mov.b64 %0, {%1,%2};" : "=l"(r) : "f"(x), "f"(y)); return r;
}
__device__ __forceinline__ ull fma2(ull a, ull b, ull c) {
    ull d; asm("fma.rn.f32x2 %0, %1, %2, %3;" : "=l"(d) : "l"(a), "l"(b), "l"(c)); return d;
}
__device__ __forceinline__ float lo2(ull v) { return __uint_as_float((unsigned)(v & 0xffffffffull)); }
__device__ __forceinline__ float hi2(ull v) { return __uint_as_float((unsigned)(v >> 32)); }
__device__ __forceinline__ void stcs32(float* p, float v) {
    asm volatile("st.global.cs.f32 [%0], %1;" :: "l"(p), "f"(v) : "memory");
}
__device__ __forceinline__ float lrelu(float x) { return x >= 0.f ? x : NEG_SLOPE * x; }
__device__ __forceinline__ float pick4(float4 v, int h) {
    float r = v.x;
    r = (h == 1) ? v.y : r;
    r = (h == 2) ? v.z : r;
    r = (h == 3) ? v.w : r;
    return r;
}

// ---------------------------------------------------------------------------
// CSR build (side stream, hidden under k1)
// ---------------------------------------------------------------------------
__global__ void k_zero(int N) {
    int i = blockIdx.x * blockDim.x + threadIdx.x;
    if (i <= N) g_cnt[i] = 0;
}

__global__ void k_count(const int* __restrict__ dst, int E) {
    int i = blockIdx.x * blockDim.x + threadIdx.x;
    int base = i * 4;
    if (base + 3 < E) {
        int4 d = *(const int4*)(dst + base);
        atomicAdd(&g_cnt[d.x], 1);
        atomicAdd(&g_cnt[d.y], 1);
        atomicAdd(&g_cnt[d.z], 1);
        atomicAdd(&g_cnt[d.w], 1);
    } else {
        for (int e = base; e < E; e++) atomicAdd(&g_cnt[dst[e]], 1);
    }
}

__global__ void k_scan1(int N) {
    __shared__ int wsum[16];
    int t = threadIdx.x;
    int idx = blockIdx.x * 512 + t;
    int lane = t & 31, w = t >> 5;
    int x = (idx <= N) ? g_cnt[idx] : 0;
    int incl = x;
#pragma unroll
    for (int d = 1; d < 32; d <<= 1) {
        int y = __shfl_up_sync(0xffffffffu, incl, d);
        if (lane >= d) incl += y;
    }
    if (lane == 31) wsum[w] = incl;
    __syncthreads();
    if (t < 32) {
        int s = (t < 16) ? wsum[t] : 0;
#pragma unroll
        for (int d = 1; d < 16; d <<= 1) {
            int y = __shfl_up_sync(0xffffffffu, s, d);
            if (t >= d) s += y;
        }
        if (t < 16) wsum[t] = s;
    }
    __syncthreads();
    int excl = (w ? wsum[w - 1] : 0) + incl - x;
    if (idx <= N) g_off[idx] = excl;
    if (t == 0) g_part[blockIdx.x] = wsum[15];
}

__global__ void k_scan2(int P) {
    __shared__ int sm[256];
    int t = threadIdx.x;
    int v = (t < P) ? g_part[t] : 0;
    sm[t] = v;
    __syncthreads();
    for (int d = 1; d < 256; d <<= 1) {
        int y = (t >= d) ? sm[t - d] : 0;
        __syncthreads();
        sm[t] += y;
        __syncthreads();
    }
    if (t < P) g_part[t] = sm[t] - v;  // exclusive
}

__global__ void k_scan3(int N) {
    int idx = blockIdx.x * 512 + threadIdx.x;
    if (idx <= N) {
        int o = g_off[idx] + g_part[blockIdx.x];
        g_off[idx] = o;
        g_cur[idx] = o;
    }
}

// scatter writes the (src, etype) payload directly in CSR order
__global__ void k_scatter(const int* __restrict__ dst, const int* __restrict__ src,
                          const int* __restrict__ efeat, int E) {
    int i = blockIdx.x * blockDim.x + threadIdx.x;
    int base = i * 4;
    if (base + 3 < E) {
        int4 d = *(const int4*)(dst + base);
        int4 s = *(const int4*)(src + base);
        int4 t = *(const int4*)(efeat + base);
        int p0 = atomicAdd(&g_cur[d.x], 1);
        int p1 = atomicAdd(&g_cur[d.y], 1);
        int p2 = atomicAdd(&g_cur[d.z], 1);
        int p3 = atomicAdd(&g_cur[d.w], 1);
        g_edge[p0] = make_int2(s.x, t.x);
        g_edge[p1] = make_int2(s.y, t.y);
        g_edge[p2] = make_int2(s.z, t.z);
        g_edge[p3] = make_int2(s.w, t.w);
    } else {
        for (int e = base; e < E; e++) {
            int p = atomicAdd(&g_cur[dst[e]], 1);
            g_edge[p] = make_int2(src[e], efeat[e]);
        }
    }
}

// ---------------------------------------------------------------------------
// ee table
// ---------------------------------------------------------------------------
__global__ void k_ee(const float* __restrict__ emb, const float* __restrict__ fce,
                     const float* __restrict__ attn_e) {
    int w = threadIdx.x >> 5;
    int lane = threadIdx.x & 31;
    if (w >= NET * H_) return;
    int et = w / H_, h = w % H_;
    float acc = 0.f;
    for (int f = lane; f < EF_; f += 32) {
        const float* row = fce + (h * EF_ + f) * EF_;
        float inner = 0.f;
#pragma unroll 8
        for (int k = 0; k < EF_; k++) inner += emb[et * EF_ + k] * row[k];
        acc += inner * attn_e[h * EF_ + f];
    }
#pragma unroll
    for (int d = 16; d; d >>= 1) acc += __shfl_xor_sync(0xffffffffu, acc, d);
    if (lane == 0) g_ee[et * H_ + h] = acc;
}

// ---------------------------------------------------------------------------
// k1: node transform + fused el/er (verified best, with register prefetch).
// ---------------------------------------------------------------------------
#define K1_SMEM_FLOATS (2 * T_ * DIN * 128 + T_ * DIN * PADN)  /* 56064 = 224256 B */
__global__ void __launch_bounds__(512) k1_transform(
    const float* __restrict__ feat, const float* __restrict__ fc,
    const float* __restrict__ resw, const float* __restrict__ attn_l,
    const float* __restrict__ attn_r, float* __restrict__ out, int N) {
    extern __shared__ float sh[];
    float* wf = sh;                          // [t*64+d][128]
    float* wr = sh + T_ * DIN * 128;
    float* sft = sh + 2 * T_ * DIN * 128;    // [t*64+d][PADN]
    for (int i = threadIdx.x; i < T_ * DIN * 128; i += blockDim.x) {
        wf[i] = fc[i];
        wr[i] = resw[i];
    }
    int lane = threadIdx.x & 31;
    int h = (threadIdx.x >> 5) & 3;
    int q = threadIdx.x >> 7;
    int j = h * 32 + lane;
    int hb = h * 96 + lane;

    int ln[3], lq[3];
#pragma unroll
    for (int k = 0; k < 3; k++) {
        int i = threadIdx.x + k * 512;
        ln[k] = i / 48;
        lq[k] = i % 48;
    }

    ull al2[T_], ar2[T_];
#pragma unroll
    for (int t = 0; t < T_; t++) {
        float a = attn_l[hb + t * 32];
        float b = attn_r[hb + t * 32];
        al2[t] = pack2(a, a);
        ar2[t] = pack2(b, b);
    }

    int step = gridDim.x * 32;
    int n0 = blockIdx.x * 32;

    float4 pre[3];
#pragma unroll
    for (int k = 0; k < 3; k++) {
        int n = n0 + ln[k];
        pre[k] = (n < N)
            ? __ldcs((const float4*)(feat + (size_t)n * FEAT_IN) + lq[k])
            : make_float4(0.f, 0.f, 0.f, 0.f);
    }
    __syncthreads();

    for (; n0 < N; n0 += step) {
        __syncthreads();
#pragma unroll
        for (int k = 0; k < 3; k++) {
            int kk = lq[k] * 4;
            sft[(kk + 0) * PADN + ln[k]] = pre[k].x;
            sft[(kk + 1) * PADN + ln[k]] = pre[k].y;
            sft[(kk + 2) * PADN + ln[k]] = pre[k].z;
            sft[(kk + 3) * PADN + ln[k]] = pre[k].w;
        }
        __syncthreads();

        int n1 = n0 + step;
        if (n1 < N) {
#pragma unroll
            for (int k = 0; k < 3; k++) {
                int n = n1 + ln[k];
                pre[k] = (n < N)
                    ? __ldcs((const float4*)(feat + (size_t)n * FEAT_IN) + lq[k])
                    : make_float4(0.f, 0.f, 0.f, 0.f);
            }
        }

        ull elp[4], erp[4];
#pragma unroll
        for (int p = 0; p < 4; p++) { elp[p] = 0ull; erp[p] = 0ull; }

#pragma unroll
        for (int t = 0; t < T_; t++) {
            ull af[4], ar[4];
#pragma unroll
            for (int p = 0; p < 4; p++) { af[p] = 0ull; ar[p] = 0ull; }
            const float* wfp = wf + (t * DIN) * 128 + j;
            const float* wrp = wr + (t * DIN) * 128 + j;
            const float* fp = sft + (t * DIN) * PADN + q * 8;
#pragma unroll 8
            for (int d = 0; d < DIN; d++) {
                float ws = wfp[(size_t)d * 128];
                float rs = wrp[(size_t)d * 128];
                ull w2f = pack2(ws, ws);
                ull w2r = pack2(rs, rs);
                ulonglong2 fv01 = *(const ulonglong2*)(fp + d * PADN);
                ulonglong2 fv23 = *(const ulonglong2*)(fp + d * PADN + 4);
                af[0] = fma2(fv01.x, w2f, af[0]);
                ar[0] = fma2(fv01.x, w2r, ar[0]);
                af[1] = fma2(fv01.y, w2f, af[1]);
                ar[1] = fma2(fv01.y, w2r, ar[1]);
                af[2] = fma2(fv23.x, w2f, af[2]);
                ar[2] = fma2(fv23.x, w2r, ar[2]);
                af[3] = fma2(fv23.y, w2f, af[3]);
                ar[3] = fma2(fv23.y, w2r, ar[3]);
            }
            int c = hb + t * 32;
#pragma unroll
            for (int p = 0; p < 4; p++) {
                elp[p] = fma2(af[p], al2[t], elp[p]);
                erp[p] = fma2(af[p], ar2[t], erp[p]);
                int n = n0 + q * 8 + 2 * p;
                if (n < N) {
                    g_ft[(size_t)n * FDIM + c] = lo2(af[p]);
                    stcs32(out + (size_t)n * FDIM + c, lo2(ar[p]));
                }
                if (n + 1 < N) {
                    g_ft[(size_t)(n + 1) * FDIM + c] = hi2(af[p]);
                    stcs32(out + (size_t)(n + 1) * FDIM + c, hi2(ar[p]));
                }
            }
        }
#pragma unroll
        for (int p = 0; p < 4; p++) {
            float e0 = lo2(elp[p]), e1 = hi2(elp[p]);
            float r0 = lo2(erp[p]), r1 = hi2(erp[p]);
#pragma unroll
            for (int d = 16; d; d >>= 1) {
                e0 += __shfl_xor_sync(0xffffffffu, e0, d);
                e1 += __shfl_xor_sync(0xffffffffu, e1, d);
                r0 += __shfl_xor_sync(0xffffffffu, r0, d);
                r1 += __shfl_xor_sync(0xffffffffu, r1, d);
            }
            if (lane == 0) {
                int n = n0 + q * 8 + 2 * p;
                if (n < N) { g_el[n * 4 + h] = e0; g_er[n * 4 + h] = r0; }
                if (n + 1 < N) { g_el[(n + 1) * 4 + h] = e1; g_er[(n + 1) * 4 + h] = r1; }
            }
        }
    }
}

// ---------------------------------------------------------------------------
// k7: softmax + aggregation. CSR payload (src,etype) read as one int2 —
// dependent-load chain shortened by one level.
// ---------------------------------------------------------------------------
__global__ void __launch_bounds__(256, 4) k7_agg(float* __restrict__ out, int N) {
    __shared__ int ssm[8][128];
    __shared__ float4 wsm[8][128];
    int wl = threadIdx.x >> 5;
    int n = (blockIdx.x * blockDim.x + threadIdx.x) >> 5;
    int lane = threadIdx.x & 31;
    if (n >= N) return;
    int s0 = g_off[n];
    int deg = g_off[n + 1] - s0;
    if (deg == 0) return;

    float4 er4 = *(const float4*)(g_er + n * 4);

    float4 vc[4];
    int sc[4];
    float4 m = make_float4(-1e30f, -1e30f, -1e30f, -1e30f);
#pragma unroll
    for (int c = 0; c < 4; c++) {
        int k = lane + 32 * c;
        sc[c] = 0;
        vc[c] = make_float4(0.f, 0.f, 0.f, 0.f);
        if (k < deg) {
            int2 se = g_edge[s0 + k];
            float4 l4 = *(const float4*)(g_el + se.x * 4);
            float4 e4 = *(const float4*)(g_ee + se.y * 4);
            float4 v;
            v.x = lrelu(l4.x + er4.x + e4.x);
            v.y = lrelu(l4.y + er4.y + e4.y);
            v.z = lrelu(l4.z + er4.z + e4.z);
            v.w = lrelu(l4.w + er4.w + e4.w);
            sc[c] = se.x;
            vc[c] = v;
            m.x = fmaxf(m.x, v.x); m.y = fmaxf(m.y, v.y);
            m.z = fmaxf(m.z, v.z); m.w = fmaxf(m.w, v.w);
        }
    }
    for (int k = lane + 128; k < deg; k += 32) {
        int2 se = g_edge[s0 + k];
        float4 l4 = *(const float4*)(g_el + se.x * 4);
        float4 e4 = *(const float4*)(g_ee + se.y * 4);
        m.x = fmaxf(m.x, lrelu(l4.x + er4.x + e4.x));
        m.y = fmaxf(m.y, lrelu(l4.y + er4.y + e4.y));
        m.z = fmaxf(m.z, lrelu(l4.z + er4.z + e4.z));
        m.w = fmaxf(m.w, lrelu(l4.w + er4.w + e4.w));
    }
#pragma unroll
    for (int d = 16; d; d >>= 1) {
        m.x = fmaxf(m.x, __shfl_xor_sync(0xffffffffu, m.x, d));
        m.y = fmaxf(m.y, __shfl_xor_sync(0xffffffffu, m.y, d));
        m.z = fmaxf(m.z, __shfl_xor_sync(0xffffffffu, m.z, d));
        m.w = fmaxf(m.w, __shfl_xor_sync(0xffffffffu, m.w, d));
    }

    float4 ss = make_float4(0.f, 0.f, 0.f, 0.f);
#pragma unroll
    for (int c = 0; c < 4; c++) {
        int k = lane + 32 * c;
        if (k < deg) {
            float4 ex;
            ex.x = __expf(vc[c].x - m.x);
            ex.y = __expf(vc[c].y - m.y);
            ex.z = __expf(vc[c].z - m.z);
            ex.w = __expf(vc[c].w - m.w);
            vc[c] = ex;
            ss.x += ex.x; ss.y += ex.y; ss.z += ex.z; ss.w += ex.w;
        }
    }
    for (int k = lane + 128; k < deg; k += 32) {
        int2 se = g_edge[s0 + k];
        float4 l4 = *(const float4*)(g_el + se.x * 4);
        float4 e4 = *(const float4*)(g_ee + se.y * 4);
        ss.x += __expf(lrelu(l4.x + er4.x + e4.x) - m.x);
        ss.y += __expf(lrelu(l4.y + er4.y + e4.y) - m.y);
        ss.z += __expf(lrelu(l4.z + er4.z + e4.z) - m.z);
        ss.w += __expf(lrelu(l4.w + er4.w + e4.w) - m.w);
    }
#pragma unroll
    for (int d = 16; d; d >>= 1) {
        ss.x += __shfl_xor_sync(0xffffffffu, ss.x, d);
        ss.y += __shfl_xor_sync(0xffffffffu, ss.y, d);
        ss.z += __shfl_xor_sync(0xffffffffu, ss.z, d);
        ss.w += __shfl_xor_sync(0xffffffffu, ss.w, d);
    }
    float4 invd = make_float4(1.f / ss.x, 1.f / ss.y, 1.f / ss.z, 1.f / ss.w);

#pragma unroll
    for (int c = 0; c < 4; c++) {
        int k = lane + 32 * c;
        if (k < deg && k < 128) {
            ssm[wl][k] = sc[c];
            wsm[wl][k] = make_float4(vc[c].x * invd.x, vc[c].y * invd.y,
                                     vc[c].z * invd.z, vc[c].w * invd.w);
        }
    }
    __syncwarp();

    int h0 = (lane * 4) / 96;
    int h1 = (128 + lane * 4) / 96;
    int h2 = (256 + lane * 4) / 96;

    float4 a0 = make_float4(0.f, 0.f, 0.f, 0.f), a1 = a0, a2 = a0;
    int total = min(deg, 128);
    int k = 0;
    for (; k + 4 <= total; k += 4) {
        int s_[4];
#pragma unroll
        for (int u = 0; u < 4; u++) s_[u] = ssm[wl][k + u];
        float4 p[4][3];
#pragma unroll
        for (int u = 0; u < 4; u++) {
            const float4* f4 = (const float4*)(g_ft + (size_t)s_[u] * FDIM);
            p[u][0] = f4[lane];
            p[u][1] = f4[32 + lane];
            p[u][2] = f4[64 + lane];
        }
#pragma unroll
        for (int u = 0; u < 4; u++) {
            float4 w4 = wsm[wl][k + u];
            float w0 = pick4(w4, h0), w1 = pick4(w4, h1), w2 = pick4(w4, h2);
            a0.x += p[u][0].x * w0; a0.y += p[u][0].y * w0; a0.z += p[u][0].z * w0; a0.w += p[u][0].w * w0;
            a1.x += p[u][1].x * w1; a1.y += p[u][1].y * w1; a1.z += p[u][1].z * w1; a1.w += p[u][1].w * w1;
            a2.x += p[u][2].x * w2; a2.y += p[u][2].y * w2; a2.z += p[u][2].z * w2; a2.w += p[u][2].w * w2;
        }
    }
    for (; k < total; k++) {
        int s = ssm[wl][k];
        float4 w4 = wsm[wl][k];
        float w0 = pick4(w4, h0), w1 = pick4(w4, h1), w2 = pick4(w4, h2);
        const float4* f4 = (const float4*)(g_ft + (size_t)s * FDIM);
        float4 p0 = f4[lane], p1 = f4[32 + lane], p2 = f4[64 + lane];
        a0.x += p0.x * w0; a0.y += p0.y * w0; a0.z += p0.z * w0; a0.w += p0.w * w0;
        a1.x += p1.x * w1; a1.y += p1.y * w1; a1.z += p1.z * w1; a1.w += p1.w * w1;
        a2.x += p2.x * w2; a2.y += p2.y * w2; a2.z += p2.z * w2; a2.w += p2.w * w2;
    }
    for (int kk = 128; kk < deg; kk++) {
        int2 se = g_edge[s0 + kk];
        int s = se.x;
        float4 l4 = *(const float4*)(g_el + s * 4);
        float4 e4 = *(const float4*)(g_ee + se.y * 4);
        float4 exv;
        exv.x = __expf(lrelu(l4.x + er4.x + e4.x) - m.x) * invd.x;
        exv.y = __expf(lrelu(l4.y + er4.y + e4.y) - m.y) * invd.y;
        exv.z = __expf(lrelu(l4.z + er4.z + e4.z) - m.z) * invd.z;
        exv.w = __expf(lrelu(l4.w + er4.w + e4.w) - m.w) * invd.w;
        float w0 = pick4(exv, h0), w1 = pick4(exv, h1), w2 = pick4(exv, h2);
        const float4* f4 = (const float4*)(g_ft + (size_t)s * FDIM);
        float4 p0 = f4[lane], p1 = f4[32 + lane], p2 = f4[64 + lane];
        a0.x += p0.x * w0; a0.y += p0.y * w0; a0.z += p0.z * w0; a0.w += p0.w * w0;
        a1.x += p1.x * w1; a1.y += p1.y * w1; a1.z += p1.z * w1; a1.w += p1.w * w1;
        a2.x += p2.x * w2; a2.y += p2.y * w2; a2.z += p2.z * w2; a2.w += p2.w * w2;
    }

    float4* o4 = (float4*)(out + (size_t)n * FDIM);
    float4 q;
    q = __ldcs(o4 + lane);
    q.x += a0.x; q.y += a0.y; q.z += a0.z; q.w += a0.w;
    __stcs(o4 + lane, q);
    q = __ldcs(o4 + 32 + lane);
    q.x += a1.x; q.y += a1.y; q.z += a1.z; q.w += a1.w;
    __stcs(o4 + 32 + lane, q);
    q = __ldcs(o4 + 64 + lane);
    q.x += a2.x; q.y += a2.y; q.z += a2.z; q.w += a2.w;
    __stcs(o4 + 64 + lane, q);
}

// ---------------------------------------------------------------------------
extern "C" void kernel_launch(void* const* d_in, const int* in_sizes, int n_in,
                              void* d_out, int out_size) {
    const float* feat   = (const float*)d_in[0];
    const int*   e_feat = (const int*)d_in[1];
    const int*   src    = (const int*)d_in[2];
    const int*   dst    = (const int*)d_in[3];
    const float* fc     = (const float*)d_in[4];
    const float* resw   = (const float*)d_in[5];
    const float* emb    = (const float*)d_in[6];
    const float* fce    = (const float*)d_in[7];
    const float* attn_l = (const float*)d_in[8];
    const float* attn_r = (const float*)d_in[9];
    const float* attn_e = (const float*)d_in[10];
    float* out = (float*)d_out;

    int N = in_sizes[0] / FEAT_IN;
    int E = in_sizes[1];

    cudaFuncSetAttribute(k1_transform, cudaFuncAttributeMaxDynamicSharedMemorySize,
                         K1_SMEM_FLOATS * (int)sizeof(float));

    int scanBlocks = (N + 1 + 511) / 512;
    cudaStream_t s = g_ss.s;

    // fork: CSR chain + ee on side stream, overlapping k1 on the main stream
    cudaEventRecord(g_ss.eFork, 0);
    cudaStreamWaitEvent(s, g_ss.eFork, 0);

    k_zero<<<(N + 256) / 256, 256, 0, s>>>(N);
    k_count<<<(E / 4 + 255) / 256, 256, 0, s>>>(dst, E);
    k_scan1<<<scanBlocks, 512, 0, s>>>(N);
    k_scan2<<<1, 256, 0, s>>>(scanBlocks);
    k_scan3<<<scanBlocks, 512, 0, s>>>(N);
    k_scatter<<<(E / 4 + 255) / 256, 256, 0, s>>>(dst, src, e_feat, E);
    k_ee<<<1, 640, 0, s>>>(emb, fce, attn_e);
    cudaEventRecord(g_ss.eJoin, s);

    // main stream: node transform (no CSR dependency)
    k1_transform<<<148, 512, K1_SMEM_FLOATS * (int)sizeof(float)>>>(
        feat, fc, resw, attn_l, attn_r, out, N);

    // join, then aggregation
    cudaStreamWaitEvent(0, g_ss.eJoin, 0);
    k7_agg<<<(N + 7) / 8, 256>>>(out, N);
}

// round 16
// speedup vs baseline: 1.2758x; 1.0041x over previous
#include <cuda_runtime.h>
#include <cuda_fp16.h>

#define T_ 3
#define H_ 4
#define DIN 64
#define FEAT_IN 192     /* T_*DIN */
#define FDIM 384        /* H_ * T_*32 */
#define EF_ 64
#define NET 5
#define MAXN 50000
#define MAXE 400000
#define NEG_SLOPE 0.2f
#define PADN 36

typedef unsigned long long ull;

__device__ float g_ft[(size_t)MAXN * FDIM];
__device__ float g_el[MAXN * H_];
__device__ float g_er[MAXN * H_];
__device__ float g_ee[32];
__device__ int   g_cnt[MAXN + 1];
__device__ int   g_off[MAXN + 1];
__device__ int   g_cur[MAXN + 1];
__device__ int2  g_edge[MAXE];   // CSR payload: {src, etype}
__device__ int   g_part[256];

// side stream + events, created once at static-init (before harness checkpoints)
struct SideStream {
    cudaStream_t s;
    cudaEvent_t eFork, eJoin;
    SideStream() {
        cudaStreamCreateWithFlags(&s, cudaStreamNonBlocking);
        cudaEventCreateWithFlags(&eFork, cudaEventDisableTiming);
        cudaEventCreateWithFlags(&eJoin, cudaEventDisableTiming);
    }
};
static SideStream g_ss;

__device__ __forceinline__ ull pack2(float x, float y) {
    ull r; asm("mov.b64 %0, {%1,%2};" : "=l"(r) : "f"(x), "f"(y)); return r;
}
__device__ __forceinline__ ull fma2(ull a, ull b, ull c) {
    ull d; asm("fma.rn.f32x2 %0, %1, %2, %3;" : "=l"(d) : "l"(a), "l"(b), "l"(c)); return d;
}
__device__ __forceinline__ float lo2(ull v) { return __uint_as_float((unsigned)(v & 0xffffffffull)); }
__device__ __forceinline__ float hi2(ull v) { return __uint_as_float((unsigned)(v >> 32)); }
__device__ __forceinline__ void stcs32(float* p, float v) {
    asm volatile("st.global.cs.f32 [%0], %1;" :: "l"(p), "f"(v) : "memory");
}
__device__ __forceinline__ float lrelu(float x) { return x >= 0.f ? x : NEG_SLOPE * x; }
__device__ __forceinline__ float pick4(float4 v, int h) {
    float r = v.x;
    r = (h == 1) ? v.y : r;
    r = (h == 2) ? v.z : r;
    r = (h == 3) ? v.w : r;
    return r;
}

// ---------------------------------------------------------------------------
// CSR build (side stream, hidden under k1)
// ---------------------------------------------------------------------------
__global__ void k_zero(int N) {
    int i = blockIdx.x * blockDim.x + threadIdx.x;
    if (i <= N) g_cnt[i] = 0;
}

__global__ void k_count(const int* __restrict__ dst, int E) {
    int i = blockIdx.x * blockDim.x + threadIdx.x;
    int base = i * 4;
    if (base + 3 < E) {
        int4 d = *(const int4*)(dst + base);
        atomicAdd(&g_cnt[d.x], 1);
        atomicAdd(&g_cnt[d.y], 1);
        atomicAdd(&g_cnt[d.z], 1);
        atomicAdd(&g_cnt[d.w], 1);
    } else {
        for (int e = base; e < E; e++) atomicAdd(&g_cnt[dst[e]], 1);
    }
}

__global__ void k_scan1(int N) {
    __shared__ int wsum[16];
    int t = threadIdx.x;
    int idx = blockIdx.x * 512 + t;
    int lane = t & 31, w = t >> 5;
    int x = (idx <= N) ? g_cnt[idx] : 0;
    int incl = x;
#pragma unroll
    for (int d = 1; d < 32; d <<= 1) {
        int y = __shfl_up_sync(0xffffffffu, incl, d);
        if (lane >= d) incl += y;
    }
    if (lane == 31) wsum[w] = incl;
    __syncthreads();
    if (t < 32) {
        int s = (t < 16) ? wsum[t] : 0;
#pragma unroll
        for (int d = 1; d < 16; d <<= 1) {
            int y = __shfl_up_sync(0xffffffffu, s, d);
            if (t >= d) s += y;
        }
        if (t < 16) wsum[t] = s;
    }
    __syncthreads();
    int excl = (w ? wsum[w - 1] : 0) + incl - x;
    if (idx <= N) g_off[idx] = excl;
    if (t == 0) g_part[blockIdx.x] = wsum[15];
}

__global__ void k_scan2(int P) {
    __shared__ int sm[256];
    int t = threadIdx.x;
    int v = (t < P) ? g_part[t] : 0;
    sm[t] = v;
    __syncthreads();
    for (int d = 1; d < 256; d <<= 1) {
        int y = (t >= d) ? sm[t - d] : 0;
        __syncthreads();
        sm[t] += y;
        __syncthreads();
    }
    if (t < P) g_part[t] = sm[t] - v;  // exclusive
}

__global__ void k_scan3(int N) {
    int idx = blockIdx.x * 512 + threadIdx.x;
    if (idx <= N) {
        int o = g_off[idx] + g_part[blockIdx.x];
        g_off[idx] = o;
        g_cur[idx] = o;
    }
}

// scatter writes the (src, etype) payload directly in CSR order
__global__ void k_scatter(const int* __restrict__ dst, const int* __restrict__ src,
                          const int* __restrict__ efeat, int E) {
    int i = blockIdx.x * blockDim.x + threadIdx.x;
    int base = i * 4;
    if (base + 3 < E) {
        int4 d = *(const int4*)(dst + base);
        int4 s = *(const int4*)(src + base);
        int4 t = *(const int4*)(efeat + base);
        int p0 = atomicAdd(&g_cur[d.x], 1);
        int p1 = atomicAdd(&g_cur[d.y], 1);
        int p2 = atomicAdd(&g_cur[d.z], 1);
        int p3 = atomicAdd(&g_cur[d.w], 1);
        g_edge[p0] = make_int2(s.x, t.x);
        g_edge[p1] = make_int2(s.y, t.y);
        g_edge[p2] = make_int2(s.z, t.z);
        g_edge[p3] = make_int2(s.w, t.w);
    } else {
        for (int e = base; e < E; e++) {
            int p = atomicAdd(&g_cur[dst[e]], 1);
            g_edge[p] = make_int2(src[e], efeat[e]);
        }
    }
}

// ---------------------------------------------------------------------------
// ee table
// ---------------------------------------------------------------------------
__global__ void k_ee(const float* __restrict__ emb, const float* __restrict__ fce,
                     const float* __restrict__ attn_e) {
    int w = threadIdx.x >> 5;
    int lane = threadIdx.x & 31;
    if (w >= NET * H_) return;
    int et = w / H_, h = w % H_;
    float acc = 0.f;
    for (int f = lane; f < EF_; f += 32) {
        const float* row = fce + (h * EF_ + f) * EF_;
        float inner = 0.f;
#pragma unroll 8
        for (int k = 0; k < EF_; k++) inner += emb[et * EF_ + k] * row[k];
        acc += inner * attn_e[h * EF_ + f];
    }
#pragma unroll
    for (int d = 16; d; d >>= 1) acc += __shfl_xor_sync(0xffffffffu, acc, d);
    if (lane == 0) g_ee[et * H_ + h] = acc;
}

// ---------------------------------------------------------------------------
// k1: node transform + fused el/er. Weights packed as half2 {fc,res} -> one
// LDS.32 per d fetches both matrices (halves weight smem traffic).
// ---------------------------------------------------------------------------
#define K1_SMEM_FLOATS (T_ * DIN * 128 + T_ * DIN * PADN)  /* 31488 = 125952 B */
__global__ void __launch_bounds__(512) k1_transform(
    const float* __restrict__ feat, const float* __restrict__ fc,
    const float* __restrict__ resw, const float* __restrict__ attn_l,
    const float* __restrict__ attn_r, float* __restrict__ out, int N) {
    extern __shared__ float sh[];
    __half2* wh = (__half2*)sh;              // [t*64+d][128] packed {fc, res}
    float* sft = sh + T_ * DIN * 128;        // [t*64+d][PADN]
    for (int i = threadIdx.x; i < T_ * DIN * 128; i += blockDim.x) {
        wh[i] = __float22half2_rn(make_float2(fc[i], resw[i]));
    }
    int lane = threadIdx.x & 31;
    int h = (threadIdx.x >> 5) & 3;
    int q = threadIdx.x >> 7;
    int j = h * 32 + lane;
    int hb = h * 96 + lane;

    int ln[3], lq[3];
#pragma unroll
    for (int k = 0; k < 3; k++) {
        int i = threadIdx.x + k * 512;
        ln[k] = i / 48;
        lq[k] = i % 48;
    }

    ull al2[T_], ar2[T_];
#pragma unroll
    for (int t = 0; t < T_; t++) {
        float a = attn_l[hb + t * 32];
        float b = attn_r[hb + t * 32];
        al2[t] = pack2(a, a);
        ar2[t] = pack2(b, b);
    }

    int step = gridDim.x * 32;
    int n0 = blockIdx.x * 32;

    float4 pre[3];
#pragma unroll
    for (int k = 0; k < 3; k++) {
        int n = n0 + ln[k];
        pre[k] = (n < N)
            ? __ldcs((const float4*)(feat + (size_t)n * FEAT_IN) + lq[k])
            : make_float4(0.f, 0.f, 0.f, 0.f);
    }
    __syncthreads();

    for (; n0 < N; n0 += step) {
        __syncthreads();
#pragma unroll
        for (int k = 0; k < 3; k++) {
            int kk = lq[k] * 4;
            sft[(kk + 0) * PADN + ln[k]] = pre[k].x;
            sft[(kk + 1) * PADN + ln[k]] = pre[k].y;
            sft[(kk + 2) * PADN + ln[k]] = pre[k].z;
            sft[(kk + 3) * PADN + ln[k]] = pre[k].w;
        }
        __syncthreads();

        int n1 = n0 + step;
        if (n1 < N) {
#pragma unroll
            for (int k = 0; k < 3; k++) {
                int n = n1 + ln[k];
                pre[k] = (n < N)
                    ? __ldcs((const float4*)(feat + (size_t)n * FEAT_IN) + lq[k])
                    : make_float4(0.f, 0.f, 0.f, 0.f);
            }
        }

        ull elp[4], erp[4];
#pragma unroll
        for (int p = 0; p < 4; p++) { elp[p] = 0ull; erp[p] = 0ull; }

#pragma unroll
        for (int t = 0; t < T_; t++) {
            ull af[4], ar[4];
#pragma unroll
            for (int p = 0; p < 4; p++) { af[p] = 0ull; ar[p] = 0ull; }
            const __half2* whp = wh + (t * DIN) * 128 + j;
            const float* fp = sft + (t * DIN) * PADN + q * 8;
#pragma unroll 8
            for (int d = 0; d < DIN; d++) {
                float2 wsr = __half22float2(whp[(size_t)d * 128]);
                ull w2f = pack2(wsr.x, wsr.x);
                ull w2r = pack2(wsr.y, wsr.y);
                ulonglong2 fv01 = *(const ulonglong2*)(fp + d * PADN);
                ulonglong2 fv23 = *(const ulonglong2*)(fp + d * PADN + 4);
                af[0] = fma2(fv01.x, w2f, af[0]);
                ar[0] = fma2(fv01.x, w2r, ar[0]);
                af[1] = fma2(fv01.y, w2f, af[1]);
                ar[1] = fma2(fv01.y, w2r, ar[1]);
                af[2] = fma2(fv23.x, w2f, af[2]);
                ar[2] = fma2(fv23.x, w2r, ar[2]);
                af[3] = fma2(fv23.y, w2f, af[3]);
                ar[3] = fma2(fv23.y, w2r, ar[3]);
            }
            int c = hb + t * 32;
#pragma unroll
            for (int p = 0; p < 4; p++) {
                elp[p] = fma2(af[p], al2[t], elp[p]);
                erp[p] = fma2(af[p], ar2[t], erp[p]);
                int n = n0 + q * 8 + 2 * p;
                if (n < N) {
                    g_ft[(size_t)n * FDIM + c] = lo2(af[p]);
                    stcs32(out + (size_t)n * FDIM + c, lo2(ar[p]));
                }
                if (n + 1 < N) {
                    g_ft[(size_t)(n + 1) * FDIM + c] = hi2(af[p]);
                    stcs32(out + (size_t)(n + 1) * FDIM + c, hi2(ar[p]));
                }
            }
        }
#pragma unroll
        for (int p = 0; p < 4; p++) {
            float e0 = lo2(elp[p]), e1 = hi2(elp[p]);
            float r0 = lo2(erp[p]), r1 = hi2(erp[p]);
#pragma unroll
            for (int d = 16; d; d >>= 1) {
                e0 += __shfl_xor_sync(0xffffffffu, e0, d);
                e1 += __shfl_xor_sync(0xffffffffu, e1, d);
                r0 += __shfl_xor_sync(0xffffffffu, r0, d);
                r1 += __shfl_xor_sync(0xffffffffu, r1, d);
            }
            if (lane == 0) {
                int n = n0 + q * 8 + 2 * p;
                if (n < N) { g_el[n * 4 + h] = e0; g_er[n * 4 + h] = r0; }
                if (n + 1 < N) { g_el[(n + 1) * 4 + h] = e1; g_er[(n + 1) * 4 + h] = r1; }
            }
        }
    }
}

// ---------------------------------------------------------------------------
// k7: softmax + aggregation (verified R15 config).
// ---------------------------------------------------------------------------
__global__ void __launch_bounds__(256, 4) k7_agg(float* __restrict__ out, int N) {
    __shared__ int ssm[8][128];
    __shared__ float4 wsm[8][128];
    int wl = threadIdx.x >> 5;
    int n = (blockIdx.x * blockDim.x + threadIdx.x) >> 5;
    int lane = threadIdx.x & 31;
    if (n >= N) return;
    int s0 = g_off[n];
    int deg = g_off[n + 1] - s0;
    if (deg == 0) return;

    float4 er4 = *(const float4*)(g_er + n * 4);

    float4 vc[4];
    int sc[4];
    float4 m = make_float4(-1e30f, -1e30f, -1e30f, -1e30f);
#pragma unroll
    for (int c = 0; c < 4; c++) {
        int k = lane + 32 * c;
        sc[c] = 0;
        vc[c] = make_float4(0.f, 0.f, 0.f, 0.f);
        if (k < deg) {
            int2 se = g_edge[s0 + k];
            float4 l4 = *(const float4*)(g_el + se.x * 4);
            float4 e4 = *(const float4*)(g_ee + se.y * 4);
            float4 v;
            v.x = lrelu(l4.x + er4.x + e4.x);
            v.y = lrelu(l4.y + er4.y + e4.y);
            v.z = lrelu(l4.z + er4.z + e4.z);
            v.w = lrelu(l4.w + er4.w + e4.w);
            sc[c] = se.x;
            vc[c] = v;
            m.x = fmaxf(m.x, v.x); m.y = fmaxf(m.y, v.y);
            m.z = fmaxf(m.z, v.z); m.w = fmaxf(m.w, v.w);
        }
    }
    for (int k = lane + 128; k < deg; k += 32) {
        int2 se = g_edge[s0 + k];
        float4 l4 = *(const float4*)(g_el + se.x * 4);
        float4 e4 = *(const float4*)(g_ee + se.y * 4);
        m.x = fmaxf(m.x, lrelu(l4.x + er4.x + e4.x));
        m.y = fmaxf(m.y, lrelu(l4.y + er4.y + e4.y));
        m.z = fmaxf(m.z, lrelu(l4.z + er4.z + e4.z));
        m.w = fmaxf(m.w, lrelu(l4.w + er4.w + e4.w));
    }
#pragma unroll
    for (int d = 16; d; d >>= 1) {
        m.x = fmaxf(m.x, __shfl_xor_sync(0xffffffffu, m.x, d));
        m.y = fmaxf(m.y, __shfl_xor_sync(0xffffffffu, m.y, d));
        m.z = fmaxf(m.z, __shfl_xor_sync(0xffffffffu, m.z, d));
        m.w = fmaxf(m.w, __shfl_xor_sync(0xffffffffu, m.w, d));
    }

    float4 ss = make_float4(0.f, 0.f, 0.f, 0.f);
#pragma unroll
    for (int c = 0; c < 4; c++) {
        int k = lane + 32 * c;
        if (k < deg) {
            float4 ex;
            ex.x = __expf(vc[c].x - m.x);
            ex.y = __expf(vc[c].y - m.y);
            ex.z = __expf(vc[c].z - m.z);
            ex.w = __expf(vc[c].w - m.w);
            vc[c] = ex;
            ss.x += ex.x; ss.y += ex.y; ss.z += ex.z; ss.w += ex.w;
        }
    }
    for (int k = lane + 128; k < deg; k += 32) {
        int2 se = g_edge[s0 + k];
        float4 l4 = *(const float4*)(g_el + se.x * 4);
        float4 e4 = *(const float4*)(g_ee + se.y * 4);
        ss.x += __expf(lrelu(l4.x + er4.x + e4.x) - m.x);
        ss.y += __expf(lrelu(l4.y + er4.y + e4.y) - m.y);
        ss.z += __expf(lrelu(l4.z + er4.z + e4.z) - m.z);
        ss.w += __expf(lrelu(l4.w + er4.w + e4.w) - m.w);
    }
#pragma unroll
    for (int d = 16; d; d >>= 1) {
        ss.x += __shfl_xor_sync(0xffffffffu, ss.x, d);
        ss.y += __shfl_xor_sync(0xffffffffu, ss.y, d);
        ss.z += __shfl_xor_sync(0xffffffffu, ss.z, d);
        ss.w += __shfl_xor_sync(0xffffffffu, ss.w, d);
    }
    float4 invd = make_float4(1.f / ss.x, 1.f / ss.y, 1.f / ss.z, 1.f / ss.w);

#pragma unroll
    for (int c = 0; c < 4; c++) {
        int k = lane + 32 * c;
        if (k < deg && k < 128) {
            ssm[wl][k] = sc[c];
            wsm[wl][k] = make_float4(vc[c].x * invd.x, vc[c].y * invd.y,
                                     vc[c].z * invd.z, vc[c].w * invd.w);
        }
    }
    __syncwarp();

    int h0 = (lane * 4) / 96;
    int h1 = (128 + lane * 4) / 96;
    int h2 = (256 + lane * 4) / 96;

    float4 a0 = make_float4(0.f, 0.f, 0.f, 0.f), a1 = a0, a2 = a0;
    int total = min(deg, 128);
    int k = 0;
    for (; k + 4 <= total; k += 4) {
        int s_[4];
#pragma unroll
        for (int u = 0; u < 4; u++) s_[u] = ssm[wl][k + u];
        float4 p[4][3];
#pragma unroll
        for (int u = 0; u < 4; u++) {
            const float4* f4 = (const float4*)(g_ft + (size_t)s_[u] * FDIM);
            p[u][0] = f4[lane];
            p[u][1] = f4[32 + lane];
            p[u][2] = f4[64 + lane];
        }
#pragma unroll
        for (int u = 0; u < 4; u++) {
            float4 w4 = wsm[wl][k + u];
            float w0 = pick4(w4, h0), w1 = pick4(w4, h1), w2 = pick4(w4, h2);
            a0.x += p[u][0].x * w0; a0.y += p[u][0].y * w0; a0.z += p[u][0].z * w0; a0.w += p[u][0].w * w0;
            a1.x += p[u][1].x * w1; a1.y += p[u][1].y * w1; a1.z += p[u][1].z * w1; a1.w += p[u][1].w * w1;
            a2.x += p[u][2].x * w2; a2.y += p[u][2].y * w2; a2.z += p[u][2].z * w2; a2.w += p[u][2].w * w2;
        }
    }
    for (; k < total; k++) {
        int s = ssm[wl][k];
        float4 w4 = wsm[wl][k];
        float w0 = pick4(w4, h0), w1 = pick4(w4, h1), w2 = pick4(w4, h2);
        const float4* f4 = (const float4*)(g_ft + (size_t)s * FDIM);
        float4 p0 = f4[lane], p1 = f4[32 + lane], p2 = f4[64 + lane];
        a0.x += p0.x * w0; a0.y += p0.y * w0; a0.z += p0.z * w0; a0.w += p0.w * w0;
        a1.x += p1.x * w1; a1.y += p1.y * w1; a1.z += p1.z * w1; a1.w += p1.w * w1;
        a2.x += p2.x * w2; a2.y += p2.y * w2; a2.z += p2.z * w2; a2.w += p2.w * w2;
    }
    for (int kk = 128; kk < deg; kk++) {
        int2 se = g_edge[s0 + kk];
        int s = se.x;
        float4 l4 = *(const float4*)(g_el + s * 4);
        float4 e4 = *(const float4*)(g_ee + se.y * 4);
        float4 exv;
        exv.x = __expf(lrelu(l4.x + er4.x + e4.x) - m.x) * invd.x;
        exv.y = __expf(lrelu(l4.y + er4.y + e4.y) - m.y) * invd.y;
        exv.z = __expf(lrelu(l4.z + er4.z + e4.z) - m.z) * invd.z;
        exv.w = __expf(lrelu(l4.w + er4.w + e4.w) - m.w) * invd.w;
        float w0 = pick4(exv, h0), w1 = pick4(exv, h1), w2 = pick4(exv, h2);
        const float4* f4 = (const float4*)(g_ft + (size_t)s * FDIM);
        float4 p0 = f4[lane], p1 = f4[32 + lane], p2 = f4[64 + lane];
        a0.x += p0.x * w0; a0.y += p0.y * w0; a0.z += p0.z * w0; a0.w += p0.w * w0;
        a1.x += p1.x * w1; a1.y += p1.y * w1; a1.z += p1.z * w1; a1.w += p1.w * w1;
        a2.x += p2.x * w2; a2.y += p2.y * w2; a2.z += p2.z * w2; a2.w += p2.w * w2;
    }

    float4* o4 = (float4*)(out + (size_t)n * FDIM);
    float4 q;
    q = __ldcs(o4 + lane);
    q.x += a0.x; q.y += a0.y; q.z += a0.z; q.w += a0.w;
    __stcs(o4 + lane, q);
    q = __ldcs(o4 + 32 + lane);
    q.x += a1.x; q.y += a1.y; q.z += a1.z; q.w += a1.w;
    __stcs(o4 + 32 + lane, q);
    q = __ldcs(o4 + 64 + lane);
    q.x += a2.x; q.y += a2.y; q.z += a2.z; q.w += a2.w;
    __stcs(o4 + 64 + lane, q);
}

// ---------------------------------------------------------------------------
extern "C" void kernel_launch(void* const* d_in, const int* in_sizes, int n_in,
                              void* d_out, int out_size) {
    const float* feat   = (const float*)d_in[0];
    const int*   e_feat = (const int*)d_in[1];
    const int*   src    = (const int*)d_in[2];
    const int*   dst    = (const int*)d_in[3];
    const float* fc     = (const float*)d_in[4];
    const float* resw   = (const float*)d_in[5];
    const float* emb    = (const float*)d_in[6];
    const float* fce    = (const float*)d_in[7];
    const float* attn_l = (const float*)d_in[8];
    const float* attn_r = (const float*)d_in[9];
    const float* attn_e = (const float*)d_in[10];
    float* out = (float*)d_out;

    int N = in_sizes[0] / FEAT_IN;
    int E = in_sizes[1];

    cudaFuncSetAttribute(k1_transform, cudaFuncAttributeMaxDynamicSharedMemorySize,
                         K1_SMEM_FLOATS * (int)sizeof(float));

    int scanBlocks = (N + 1 + 511) / 512;
    cudaStream_t s = g_ss.s;

    // fork: CSR chain + ee on side stream, overlapping k1 on the main stream
    cudaEventRecord(g_ss.eFork, 0);
    cudaStreamWaitEvent(s, g_ss.eFork, 0);

    k_zero<<<(N + 256) / 256, 256, 0, s>>>(N);
    k_count<<<(E / 4 + 255) / 256, 256, 0, s>>>(dst, E);
    k_scan1<<<scanBlocks, 512, 0, s>>>(N);
    k_scan2<<<1, 256, 0, s>>>(scanBlocks);
    k_scan3<<<scanBlocks, 512, 0, s>>>(N);
    k_scatter<<<(E / 4 + 255) / 256, 256, 0, s>>>(dst, src, e_feat, E);
    k_ee<<<1, 640, 0, s>>>(emb, fce, attn_e);
    cudaEventRecord(g_ss.eJoin, s);

    // main stream: node transform (no CSR dependency)
    k1_transform<<<148, 512, K1_SMEM_FLOATS * (int)sizeof(float)>>>(
        feat, fc, resw, attn_l, attn_r, out, N);

    // join, then aggregation
    cudaStreamWaitEvent(0, g_ss.eJoin, 0);
    k7_agg<<<(N + 7) / 8, 256>>>(out, N);
}

// round 17
// speedup vs baseline: 1.4196x; 1.1127x over previous
#include <cuda_runtime.h>
#include <cuda_fp16.h>

#define T_ 3
#define H_ 4
#define DIN 64
#define FEAT_IN 192     /* T_*DIN */
#define FDIM 384        /* H_ * T_*32 */
#define EF_ 64
#define NET 5
#define MAXN 50000
#define MAXE 400000
#define NEG_SLOPE 0.2f
#define PADN 36

typedef unsigned long long ull;

__device__ __half g_fth[(size_t)MAXN * FDIM];   // ft in fp16 (38 MB, L2-resident)
__device__ float g_el[MAXN * H_];
__device__ float g_er[MAXN * H_];
__device__ float g_ee[32];
__device__ int   g_cnt[MAXN + 1];
__device__ int   g_off[MAXN + 1];
__device__ int   g_cur[MAXN + 1];
__device__ int2  g_edge[MAXE];   // CSR payload: {src, etype}
__device__ int   g_part[256];

// side stream + events, created once at static-init (before harness checkpoints)
struct SideStream {
    cudaStream_t s;
    cudaEvent_t eFork, eJoin;
    SideStream() {
        cudaStreamCreateWithFlags(&s, cudaStreamNonBlocking);
        cudaEventCreateWithFlags(&eFork, cudaEventDisableTiming);
        cudaEventCreateWithFlags(&eJoin, cudaEventDisableTiming);
    }
};
static SideStream g_ss;

__device__ __forceinline__ ull pack2(float x, float y) {
    ull r; asm("mov.b64 %0, {%1,%2};" : "=l"(r) : "f"(x), "f"(y)); return r;
}
__device__ __forceinline__ ull fma2(ull a, ull b, ull c) {
    ull d; asm("fma.rn.f32x2 %0, %1, %2, %3;" : "=l"(d) : "l"(a), "l"(b), "l"(c)); return d;
}
__device__ __forceinline__ float lo2(ull v) { return __uint_as_float((unsigned)(v & 0xffffffffull)); }
__device__ __forceinline__ float hi2(ull v) { return __uint_as_float((unsigned)(v >> 32)); }
__device__ __forceinline__ void stcs32(float* p, float v) {
    asm volatile("st.global.cs.f32 [%0], %1;" :: "l"(p), "f"(v) : "memory");
}
__device__ __forceinline__ float lrelu(float x) { return x >= 0.f ? x : NEG_SLOPE * x; }
__device__ __forceinline__ float pick4(float4 v, int h) {
    float r = v.x;
    r = (h == 1) ? v.y : r;
    r = (h == 2) ? v.z : r;
    r = (h == 3) ? v.w : r;
    return r;
}
// load 4 consecutive fp16 ft columns as float4
__device__ __forceinline__ float4 ldft4(const __half* p) {
    uint2 u = *(const uint2*)p;
    __half2 a = *(__half2*)&u.x;
    __half2 b = *(__half2*)&u.y;
    float2 f0 = __half22float2(a);
    float2 f1 = __half22float2(b);
    return make_float4(f0.x, f0.y, f1.x, f1.y);
}

// ---------------------------------------------------------------------------
// CSR build (side stream, hidden under k1)
// ---------------------------------------------------------------------------
__global__ void k_zero(int N) {
    int i = blockIdx.x * blockDim.x + threadIdx.x;
    if (i <= N) g_cnt[i] = 0;
}

__global__ void k_count(const int* __restrict__ dst, int E) {
    int i = blockIdx.x * blockDim.x + threadIdx.x;
    int base = i * 4;
    if (base + 3 < E) {
        int4 d = *(const int4*)(dst + base);
        atomicAdd(&g_cnt[d.x], 1);
        atomicAdd(&g_cnt[d.y], 1);
        atomicAdd(&g_cnt[d.z], 1);
        atomicAdd(&g_cnt[d.w], 1);
    } else {
        for (int e = base; e < E; e++) atomicAdd(&g_cnt[dst[e]], 1);
    }
}

__global__ void k_scan1(int N) {
    __shared__ int wsum[16];
    int t = threadIdx.x;
    int idx = blockIdx.x * 512 + t;
    int lane = t & 31, w = t >> 5;
    int x = (idx <= N) ? g_cnt[idx] : 0;
    int incl = x;
#pragma unroll
    for (int d = 1; d < 32; d <<= 1) {
        int y = __shfl_up_sync(0xffffffffu, incl, d);
        if (lane >= d) incl += y;
    }
    if (lane == 31) wsum[w] = incl;
    __syncthreads();
    if (t < 32) {
        int s = (t < 16) ? wsum[t] : 0;
#pragma unroll
        for (int d = 1; d < 16; d <<= 1) {
            int y = __shfl_up_sync(0xffffffffu, s, d);
            if (t >= d) s += y;
        }
        if (t < 16) wsum[t] = s;
    }
    __syncthreads();
    int excl = (w ? wsum[w - 1] : 0) + incl - x;
    if (idx <= N) g_off[idx] = excl;
    if (t == 0) g_part[blockIdx.x] = wsum[15];
}

__global__ void k_scan2(int P) {
    __shared__ int sm[256];
    int t = threadIdx.x;
    int v = (t < P) ? g_part[t] : 0;
    sm[t] = v;
    __syncthreads();
    for (int d = 1; d < 256; d <<= 1) {
        int y = (t >= d) ? sm[t - d] : 0;
        __syncthreads();
        sm[t] += y;
        __syncthreads();
    }
    if (t < P) g_part[t] = sm[t] - v;  // exclusive
}

__global__ void k_scan3(int N) {
    int idx = blockIdx.x * 512 + threadIdx.x;
    if (idx <= N) {
        int o = g_off[idx] + g_part[blockIdx.x];
        g_off[idx] = o;
        g_cur[idx] = o;
    }
}

__global__ void k_scatter(const int* __restrict__ dst, const int* __restrict__ src,
                          const int* __restrict__ efeat, int E) {
    int i = blockIdx.x * blockDim.x + threadIdx.x;
    int base = i * 4;
    if (base + 3 < E) {
        int4 d = *(const int4*)(dst + base);
        int4 s = *(const int4*)(src + base);
        int4 t = *(const int4*)(efeat + base);
        int p0 = atomicAdd(&g_cur[d.x], 1);
        int p1 = atomicAdd(&g_cur[d.y], 1);
        int p2 = atomicAdd(&g_cur[d.z], 1);
        int p3 = atomicAdd(&g_cur[d.w], 1);
        g_edge[p0] = make_int2(s.x, t.x);
        g_edge[p1] = make_int2(s.y, t.y);
        g_edge[p2] = make_int2(s.z, t.z);
        g_edge[p3] = make_int2(s.w, t.w);
    } else {
        for (int e = base; e < E; e++) {
            int p = atomicAdd(&g_cur[dst[e]], 1);
            g_edge[p] = make_int2(src[e], efeat[e]);
        }
    }
}

// ---------------------------------------------------------------------------
// ee table
// ---------------------------------------------------------------------------
__global__ void k_ee(const float* __restrict__ emb, const float* __restrict__ fce,
                     const float* __restrict__ attn_e) {
    int w = threadIdx.x >> 5;
    int lane = threadIdx.x & 31;
    if (w >= NET * H_) return;
    int et = w / H_, h = w % H_;
    float acc = 0.f;
    for (int f = lane; f < EF_; f += 32) {
        const float* row = fce + (h * EF_ + f) * EF_;
        float inner = 0.f;
#pragma unroll 8
        for (int k = 0; k < EF_; k++) inner += emb[et * EF_ + k] * row[k];
        acc += inner * attn_e[h * EF_ + f];
    }
#pragma unroll
    for (int d = 16; d; d >>= 1) acc += __shfl_xor_sync(0xffffffffu, acc, d);
    if (lane == 0) g_ee[et * H_ + h] = acc;
}

// ---------------------------------------------------------------------------
// k1: node transform + fused el/er (fp32 weights, verified best layout).
// ft stored as fp16 to g_fth; residual fp32 to out; el/er fp32.
// ---------------------------------------------------------------------------
#define K1_SMEM_FLOATS (2 * T_ * DIN * 128 + T_ * DIN * PADN)  /* 56064 = 224256 B */
__global__ void __launch_bounds__(512) k1_transform(
    const float* __restrict__ feat, const float* __restrict__ fc,
    const float* __restrict__ resw, const float* __restrict__ attn_l,
    const float* __restrict__ attn_r, float* __restrict__ out, int N) {
    extern __shared__ float sh[];
    float* wf = sh;                          // [t*64+d][128]
    float* wr = sh + T_ * DIN * 128;
    float* sft = sh + 2 * T_ * DIN * 128;    // [t*64+d][PADN]
    for (int i = threadIdx.x; i < T_ * DIN * 128; i += blockDim.x) {
        wf[i] = fc[i];
        wr[i] = resw[i];
    }
    int lane = threadIdx.x & 31;
    int h = (threadIdx.x >> 5) & 3;
    int q = threadIdx.x >> 7;
    int j = h * 32 + lane;
    int hb = h * 96 + lane;

    int ln[3], lq[3];
#pragma unroll
    for (int k = 0; k < 3; k++) {
        int i = threadIdx.x + k * 512;
        ln[k] = i / 48;
        lq[k] = i % 48;
    }

    ull al2[T_], ar2[T_];
#pragma unroll
    for (int t = 0; t < T_; t++) {
        float a = attn_l[hb + t * 32];
        float b = attn_r[hb + t * 32];
        al2[t] = pack2(a, a);
        ar2[t] = pack2(b, b);
    }

    int step = gridDim.x * 32;
    int n0 = blockIdx.x * 32;

    float4 pre[3];
#pragma unroll
    for (int k = 0; k < 3; k++) {
        int n = n0 + ln[k];
        pre[k] = (n < N)
            ? __ldcs((const float4*)(feat + (size_t)n * FEAT_IN) + lq[k])
            : make_float4(0.f, 0.f, 0.f, 0.f);
    }
    __syncthreads();

    for (; n0 < N; n0 += step) {
        __syncthreads();
#pragma unroll
        for (int k = 0; k < 3; k++) {
            int kk = lq[k] * 4;
            sft[(kk + 0) * PADN + ln[k]] = pre[k].x;
            sft[(kk + 1) * PADN + ln[k]] = pre[k].y;
            sft[(kk + 2) * PADN + ln[k]] = pre[k].z;
            sft[(kk + 3) * PADN + ln[k]] = pre[k].w;
        }
        __syncthreads();

        int n1 = n0 + step;
        if (n1 < N) {
#pragma unroll
            for (int k = 0; k < 3; k++) {
                int n = n1 + ln[k];
                pre[k] = (n < N)
                    ? __ldcs((const float4*)(feat + (size_t)n * FEAT_IN) + lq[k])
                    : make_float4(0.f, 0.f, 0.f, 0.f);
            }
        }

        ull elp[4], erp[4];
#pragma unroll
        for (int p = 0; p < 4; p++) { elp[p] = 0ull; erp[p] = 0ull; }

#pragma unroll
        for (int t = 0; t < T_; t++) {
            ull af[4], ar[4];
#pragma unroll
            for (int p = 0; p < 4; p++) { af[p] = 0ull; ar[p] = 0ull; }
            const float* wfp = wf + (t * DIN) * 128 + j;
            const float* wrp = wr + (t * DIN) * 128 + j;
            const float* fp = sft + (t * DIN) * PADN + q * 8;
#pragma unroll 8
            for (int d = 0; d < DIN; d++) {
                float ws = wfp[(size_t)d * 128];
                float rs = wrp[(size_t)d * 128];
                ull w2f = pack2(ws, ws);
                ull w2r = pack2(rs, rs);
                ulonglong2 fv01 = *(const ulonglong2*)(fp + d * PADN);
                ulonglong2 fv23 = *(const ulonglong2*)(fp + d * PADN + 4);
                af[0] = fma2(fv01.x, w2f, af[0]);
                ar[0] = fma2(fv01.x, w2r, ar[0]);
                af[1] = fma2(fv01.y, w2f, af[1]);
                ar[1] = fma2(fv01.y, w2r, ar[1]);
                af[2] = fma2(fv23.x, w2f, af[2]);
                ar[2] = fma2(fv23.x, w2r, ar[2]);
                af[3] = fma2(fv23.y, w2f, af[3]);
                ar[3] = fma2(fv23.y, w2r, ar[3]);
            }
            int c = hb + t * 32;
#pragma unroll
            for (int p = 0; p < 4; p++) {
                elp[p] = fma2(af[p], al2[t], elp[p]);
                erp[p] = fma2(af[p], ar2[t], erp[p]);
                int n = n0 + q * 8 + 2 * p;
                if (n < N) {
                    g_fth[(size_t)n * FDIM + c] = __float2half(lo2(af[p]));
                    stcs32(out + (size_t)n * FDIM + c, lo2(ar[p]));
                }
                if (n + 1 < N) {
                    g_fth[(size_t)(n + 1) * FDIM + c] = __float2half(hi2(af[p]));
                    stcs32(out + (size_t)(n + 1) * FDIM + c, hi2(ar[p]));
                }
            }
        }
#pragma unroll
        for (int p = 0; p < 4; p++) {
            float e0 = lo2(elp[p]), e1 = hi2(elp[p]);
            float r0 = lo2(erp[p]), r1 = hi2(erp[p]);
#pragma unroll
            for (int d = 16; d; d >>= 1) {
                e0 += __shfl_xor_sync(0xffffffffu, e0, d);
                e1 += __shfl_xor_sync(0xffffffffu, e1, d);
                r0 += __shfl_xor_sync(0xffffffffu, r0, d);
                r1 += __shfl_xor_sync(0xffffffffu, r1, d);
            }
            if (lane == 0) {
                int n = n0 + q * 8 + 2 * p;
                if (n < N) { g_el[n * 4 + h] = e0; g_er[n * 4 + h] = r0; }
                if (n + 1 < N) { g_el[(n + 1) * 4 + h] = e1; g_er[(n + 1) * 4 + h] = r1; }
            }
        }
    }
}

// ---------------------------------------------------------------------------
// k7: softmax + aggregation; ft gathered as fp16 (half the bytes).
// ---------------------------------------------------------------------------
__global__ void __launch_bounds__(256, 4) k7_agg(float* __restrict__ out, int N) {
    __shared__ int ssm[8][128];
    __shared__ float4 wsm[8][128];
    int wl = threadIdx.x >> 5;
    int n = (blockIdx.x * blockDim.x + threadIdx.x) >> 5;
    int lane = threadIdx.x & 31;
    if (n >= N) return;
    int s0 = g_off[n];
    int deg = g_off[n + 1] - s0;
    if (deg == 0) return;

    float4 er4 = *(const float4*)(g_er + n * 4);

    float4 vc[4];
    int sc[4];
    float4 m = make_float4(-1e30f, -1e30f, -1e30f, -1e30f);
#pragma unroll
    for (int c = 0; c < 4; c++) {
        int k = lane + 32 * c;
        sc[c] = 0;
        vc[c] = make_float4(0.f, 0.f, 0.f, 0.f);
        if (k < deg) {
            int2 se = g_edge[s0 + k];
            float4 l4 = *(const float4*)(g_el + se.x * 4);
            float4 e4 = *(const float4*)(g_ee + se.y * 4);
            float4 v;
            v.x = lrelu(l4.x + er4.x + e4.x);
            v.y = lrelu(l4.y + er4.y + e4.y);
            v.z = lrelu(l4.z + er4.z + e4.z);
            v.w = lrelu(l4.w + er4.w + e4.w);
            sc[c] = se.x;
            vc[c] = v;
            m.x = fmaxf(m.x, v.x); m.y = fmaxf(m.y, v.y);
            m.z = fmaxf(m.z, v.z); m.w = fmaxf(m.w, v.w);
        }
    }
    for (int k = lane + 128; k < deg; k += 32) {
        int2 se = g_edge[s0 + k];
        float4 l4 = *(const float4*)(g_el + se.x * 4);
        float4 e4 = *(const float4*)(g_ee + se.y * 4);
        m.x = fmaxf(m.x, lrelu(l4.x + er4.x + e4.x));
        m.y = fmaxf(m.y, lrelu(l4.y + er4.y + e4.y));
        m.z = fmaxf(m.z, lrelu(l4.z + er4.z + e4.z));
        m.w = fmaxf(m.w, lrelu(l4.w + er4.w + e4.w));
    }
#pragma unroll
    for (int d = 16; d; d >>= 1) {
        m.x = fmaxf(m.x, __shfl_xor_sync(0xffffffffu, m.x, d));
        m.y = fmaxf(m.y, __shfl_xor_sync(0xffffffffu, m.y, d));
        m.z = fmaxf(m.z, __shfl_xor_sync(0xffffffffu, m.z, d));
        m.w = fmaxf(m.w, __shfl_xor_sync(0xffffffffu, m.w, d));
    }

    float4 ss = make_float4(0.f, 0.f, 0.f, 0.f);
#pragma unroll
    for (int c = 0; c < 4; c++) {
        int k = lane + 32 * c;
        if (k < deg) {
            float4 ex;
            ex.x = __expf(vc[c].x - m.x);
            ex.y = __expf(vc[c].y - m.y);
            ex.z = __expf(vc[c].z - m.z);
            ex.w = __expf(vc[c].w - m.w);
            vc[c] = ex;
            ss.x += ex.x; ss.y += ex.y; ss.z += ex.z; ss.w += ex.w;
        }
    }
    for (int k = lane + 128; k < deg; k += 32) {
        int2 se = g_edge[s0 + k];
        float4 l4 = *(const float4*)(g_el + se.x * 4);
        float4 e4 = *(const float4*)(g_ee + se.y * 4);
        ss.x += __expf(lrelu(l4.x + er4.x + e4.x) - m.x);
        ss.y += __expf(lrelu(l4.y + er4.y + e4.y) - m.y);
        ss.z += __expf(lrelu(l4.z + er4.z + e4.z) - m.z);
        ss.w += __expf(lrelu(l4.w + er4.w + e4.w) - m.w);
    }
#pragma unroll
    for (int d = 16; d; d >>= 1) {
        ss.x += __shfl_xor_sync(0xffffffffu, ss.x, d);
        ss.y += __shfl_xor_sync(0xffffffffu, ss.y, d);
        ss.z += __shfl_xor_sync(0xffffffffu, ss.z, d);
        ss.w += __shfl_xor_sync(0xffffffffu, ss.w, d);
    }
    float4 invd = make_float4(1.f / ss.x, 1.f / ss.y, 1.f / ss.z, 1.f / ss.w);

#pragma unroll
    for (int c = 0; c < 4; c++) {
        int k = lane + 32 * c;
        if (k < deg && k < 128) {
            ssm[wl][k] = sc[c];
            wsm[wl][k] = make_float4(vc[c].x * invd.x, vc[c].y * invd.y,
                                     vc[c].z * invd.z, vc[c].w * invd.w);
        }
    }
    __syncwarp();

    int h0 = (lane * 4) / 96;
    int h1 = (128 + lane * 4) / 96;
    int h2 = (256 + lane * 4) / 96;

    float4 a0 = make_float4(0.f, 0.f, 0.f, 0.f), a1 = a0, a2 = a0;
    int total = min(deg, 128);
    int k = 0;
    for (; k + 4 <= total; k += 4) {
        int s_[4];
#pragma unroll
        for (int u = 0; u < 4; u++) s_[u] = ssm[wl][k + u];
        float4 p[4][3];
#pragma unroll
        for (int u = 0; u < 4; u++) {
            const __half* fh = g_fth + (size_t)s_[u] * FDIM;
            p[u][0] = ldft4(fh + lane * 4);
            p[u][1] = ldft4(fh + 128 + lane * 4);
            p[u][2] = ldft4(fh + 256 + lane * 4);
        }
#pragma unroll
        for (int u = 0; u < 4; u++) {
            float4 w4 = wsm[wl][k + u];
            float w0 = pick4(w4, h0), w1 = pick4(w4, h1), w2 = pick4(w4, h2);
            a0.x += p[u][0].x * w0; a0.y += p[u][0].y * w0; a0.z += p[u][0].z * w0; a0.w += p[u][0].w * w0;
            a1.x += p[u][1].x * w1; a1.y += p[u][1].y * w1; a1.z += p[u][1].z * w1; a1.w += p[u][1].w * w1;
            a2.x += p[u][2].x * w2; a2.y += p[u][2].y * w2; a2.z += p[u][2].z * w2; a2.w += p[u][2].w * w2;
        }
    }
    for (; k < total; k++) {
        int s = ssm[wl][k];
        float4 w4 = wsm[wl][k];
        float w0 = pick4(w4, h0), w1 = pick4(w4, h1), w2 = pick4(w4, h2);
        const __half* fh = g_fth + (size_t)s * FDIM;
        float4 p0 = ldft4(fh + lane * 4);
        float4 p1 = ldft4(fh + 128 + lane * 4);
        float4 p2 = ldft4(fh + 256 + lane * 4);
        a0.x += p0.x * w0; a0.y += p0.y * w0; a0.z += p0.z * w0; a0.w += p0.w * w0;
        a1.x += p1.x * w1; a1.y += p1.y * w1; a1.z += p1.z * w1; a1.w += p1.w * w1;
        a2.x += p2.x * w2; a2.y += p2.y * w2; a2.z += p2.z * w2; a2.w += p2.w * w2;
    }
    for (int kk = 128; kk < deg; kk++) {
        int2 se = g_edge[s0 + kk];
        int s = se.x;
        float4 l4 = *(const float4*)(g_el + s * 4);
        float4 e4 = *(const float4*)(g_ee + se.y * 4);
        float4 exv;
        exv.x = __expf(lrelu(l4.x + er4.x + e4.x) - m.x) * invd.x;
        exv.y = __expf(lrelu(l4.y + er4.y + e4.y) - m.y) * invd.y;
        exv.z = __expf(lrelu(l4.z + er4.z + e4.z) - m.z) * invd.z;
        exv.w = __expf(lrelu(l4.w + er4.w + e4.w) - m.w) * invd.w;
        float w0 = pick4(exv, h0), w1 = pick4(exv, h1), w2 = pick4(exv, h2);
        const __half* fh = g_fth + (size_t)s * FDIM;
        float4 p0 = ldft4(fh + lane * 4);
        float4 p1 = ldft4(fh + 128 + lane * 4);
        float4 p2 = ldft4(fh + 256 + lane * 4);
        a0.x += p0.x * w0; a0.y += p0.y * w0; a0.z += p0.z * w0; a0.w += p0.w * w0;
        a1.x += p1.x * w1; a1.y += p1.y * w1; a1.z += p1.z * w1; a1.w += p1.w * w1;
        a2.x += p2.x * w2; a2.y += p2.y * w2; a2.z += p2.z * w2; a2.w += p2.w * w2;
    }

    float4* o4 = (float4*)(out + (size_t)n * FDIM);
    float4 q;
    q = __ldcs(o4 + lane);
    q.x += a0.x; q.y += a0.y; q.z += a0.z; q.w += a0.w;
    __stcs(o4 + lane, q);
    q = __ldcs(o4 + 32 + lane);
    q.x += a1.x; q.y += a1.y; q.z += a1.z; q.w += a1.w;
    __stcs(o4 + 32 + lane, q);
    q = __ldcs(o4 + 64 + lane);
    q.x += a2.x; q.y += a2.y; q.z += a2.z; q.w += a2.w;
    __stcs(o4 + 64 + lane, q);
}

// ---------------------------------------------------------------------------
extern "C" void kernel_launch(void* const* d_in, const int* in_sizes, int n_in,
                              void* d_out, int out_size) {
    const float* feat   = (const float*)d_in[0];
    const int*   e_feat = (const int*)d_in[1];
    const int*   src    = (const int*)d_in[2];
    const int*   dst    = (const int*)d_in[3];
    const float* fc     = (const float*)d_in[4];
    const float* resw   = (const float*)d_in[5];
    const float* emb    = (const float*)d_in[6];
    const float* fce    = (const float*)d_in[7];
    const float* attn_l = (const float*)d_in[8];
    const float* attn_r = (const float*)d_in[9];
    const float* attn_e = (const float*)d_in[10];
    float* out = (float*)d_out;

    int N = in_sizes[0] / FEAT_IN;
    int E = in_sizes[1];

    cudaFuncSetAttribute(k1_transform, cudaFuncAttributeMaxDynamicSharedMemorySize,
                         K1_SMEM_FLOATS * (int)sizeof(float));

    int scanBlocks = (N + 1 + 511) / 512;
    cudaStream_t s = g_ss.s;

    // fork: CSR chain + ee on side stream, overlapping k1 on the main stream
    cudaEventRecord(g_ss.eFork, 0);
    cudaStreamWaitEvent(s, g_ss.eFork, 0);

    k_zero<<<(N + 256) / 256, 256, 0, s>>>(N);
    k_count<<<(E / 4 + 255) / 256, 256, 0, s>>>(dst, E);
    k_scan1<<<scanBlocks, 512, 0, s>>>(N);
    k_scan2<<<1, 256, 0, s>>>(scanBlocks);
    k_scan3<<<scanBlocks, 512, 0, s>>>(N);
    k_scatter<<<(E / 4 + 255) / 256, 256, 0, s>>>(dst, src, e_feat, E);
    k_ee<<<1, 640, 0, s>>>(emb, fce, attn_e);
    cudaEventRecord(g_ss.eJoin, s);

    // main stream: node transform (no CSR dependency)
    k1_transform<<<148, 512, K1_SMEM_FLOATS * (int)sizeof(float)>>>(
        feat, fc, resw, attn_l, attn_r, out, N);

    // join, then aggregation
    cudaStreamWaitEvent(0, g_ss.eJoin, 0);
    k7_agg<<<(N + 7) / 8, 256>>>(out, N);
}